// round 4
// baseline (speedup 1.0000x reference)
#include <cuda_runtime.h>
#include <math.h>

#define BATCH 64
#define TT 512
#define LL 4
#define II 4
#define NN 520          // TT+LL+II
#define HH 768
#define NH 4
#define DOUT 192
#define H4 (HH/4)

// ---------------- scratch (device globals; no allocations allowed) ----------------
__device__ float g_X[2][(size_t)BATCH*NN*HH];   // ping-pong node features
__device__ float g_H[(size_t)BATCH*NN*HH];      // h = X @ W^T
__device__ float g_as[BATCH*NN*NH];             // (h*a_s).sum(-1)
__device__ float g_ad[BATCH*NN*NH];             // (h*a_d).sum(-1)
__device__ int   g_excl[2][BATCH*TT];           // [0]=excluded label idx, [1]=excluded image idx

__device__ __forceinline__ float warpSum(float v){
    #pragma unroll
    for (int o=16;o;o>>=1) v += __shfl_xor_sync(0xffffffffu, v, o);
    return v;
}
__device__ __forceinline__ float warpMax(float v){
    #pragma unroll
    for (int o=16;o;o>>=1) v = fmaxf(v, __shfl_xor_sync(0xffffffffu, v, o));
    return v;
}
__device__ __forceinline__ float lrelu(float x){ return x > 0.f ? x : 0.2f*x; }

// ---------------- concat [text;label;image] -> X0 ----------------
__global__ void k_concat(const float4* __restrict__ text, const float4* __restrict__ lab,
                         const float4* __restrict__ img)
{
    size_t idx = (size_t)blockIdx.x*blockDim.x + threadIdx.x;
    const size_t total = (size_t)BATCH*NN*H4;
    if (idx >= total) return;
    int b = (int)(idx / (NN*H4));
    int r = (int)(idx % (NN*H4));
    int n = r / H4;
    int k = r % H4;
    float4 v;
    if (n < TT)          v = text[(size_t)b*TT*H4 + (size_t)n*H4 + k];
    else if (n < TT+LL)  v = lab [(size_t)b*LL*H4 + (size_t)(n-TT)*H4 + k];
    else                 v = img [(size_t)b*II*H4 + (size_t)(n-TT-LL)*H4 + k];
    ((float4*)g_X[0])[idx] = v;
}

// ---------------- dynamic edges: excluded (argmin-cos) label/image per text node ----------------
// top-3 of 4 == all except argmin of cos. cos = dot/(|t||r|); |t| common positive factor
// -> argmin over dot_j * (1/max(|r_j|,1e-8)).
__global__ void k_excl(const float* __restrict__ text, const float* __restrict__ lab,
                       const float* __restrict__ img)
{
    __shared__ float sh[8*HH];
    __shared__ float sinv[8];
    int b = blockIdx.x;
    int tid = threadIdx.x;
    for (int i=tid;i<LL*HH;i+=blockDim.x) sh[i]       = lab[(size_t)b*LL*HH + i];
    for (int i=tid;i<II*HH;i+=blockDim.x) sh[LL*HH+i] = img[(size_t)b*II*HH + i];
    __syncthreads();
    int wid = tid>>5, lane = tid&31;
    if (wid < 8){
        float s=0.f;
        for (int k=lane;k<HH;k+=32){ float v=sh[wid*HH+k]; s+=v*v; }
        s = warpSum(s);
        if (lane==0) sinv[wid] = 1.f / fmaxf(sqrtf(s), 1e-8f);
    }
    __syncthreads();
    for (int t=wid;t<TT;t+=8){
        const float* xr = text + (size_t)b*TT*HH + (size_t)t*HH;
        float d0=0,d1=0,d2=0,d3=0,d4=0,d5=0,d6=0,d7=0;
        for (int k=lane;k<HH;k+=32){
            float x = xr[k];
            d0+=x*sh[0*HH+k]; d1+=x*sh[1*HH+k]; d2+=x*sh[2*HH+k]; d3+=x*sh[3*HH+k];
            d4+=x*sh[4*HH+k]; d5+=x*sh[5*HH+k]; d6+=x*sh[6*HH+k]; d7+=x*sh[7*HH+k];
        }
        d0=warpSum(d0); d1=warpSum(d1); d2=warpSum(d2); d3=warpSum(d3);
        d4=warpSum(d4); d5=warpSum(d5); d6=warpSum(d6); d7=warpSum(d7);
        if (lane==0){
            float c0=d0*sinv[0], c1=d1*sinv[1], c2=d2*sinv[2], c3=d3*sinv[3];
            int el=0; float bm=c0;
            if (c1<bm){bm=c1;el=1;} if (c2<bm){bm=c2;el=2;} if (c3<bm){bm=c3;el=3;}
            g_excl[0][b*TT+t]=el;
            float e0=d4*sinv[4], e1=d5*sinv[5], e2=d6*sinv[6], e3=d7*sinv[7];
            int ei=0; bm=e0;
            if (e1<bm){bm=e1;ei=1;} if (e2<bm){bm=e2;ei=2;} if (e3<bm){bm=e3;ei=3;}
            g_excl[1][b*TT+t]=ei;
        }
    }
}

// ---------------- GEMM: g_H[m, j] = sum_k g_X[cur][m, k] * W[j, k] ----------------
// 128x128 tile, BK=8, 256 threads, 8x8 microtile (4+4 split for conflict-free LDS.128),
// register prefetch of next global tiles.
__global__ __launch_bounds__(256) void k_gemm(int cur, const float* __restrict__ Bw)
{
    const float* A = g_X[cur];
    float* C = g_H;
    __shared__ float As[8][128];
    __shared__ float Bs[8][128];
    int tid = threadIdx.x;
    int tx = tid & 15, ty = tid >> 4;
    int lrow = tid >> 1;
    int lk = (tid & 1) << 2;
    const float* Ap = A  + (size_t)(blockIdx.x*128 + lrow)*HH + lk;
    const float* Bp = Bw + (size_t)(blockIdx.y*128 + lrow)*HH + lk;

    float acc[8][8];
    #pragma unroll
    for (int i=0;i<8;i++)
        #pragma unroll
        for (int j=0;j<8;j++) acc[i][j]=0.f;

    float4 av = *(const float4*)Ap;
    float4 bv = *(const float4*)Bp;
    for (int k0=0;k0<HH;k0+=8){
        As[lk+0][lrow]=av.x; As[lk+1][lrow]=av.y; As[lk+2][lrow]=av.z; As[lk+3][lrow]=av.w;
        Bs[lk+0][lrow]=bv.x; Bs[lk+1][lrow]=bv.y; Bs[lk+2][lrow]=bv.z; Bs[lk+3][lrow]=bv.w;
        __syncthreads();
        if (k0+8 < HH){
            av = *(const float4*)(Ap + k0 + 8);
            bv = *(const float4*)(Bp + k0 + 8);
        }
        #pragma unroll
        for (int kk=0;kk<8;kk++){
            float4 A0 = *(const float4*)&As[kk][ty*4];
            float4 A1 = *(const float4*)&As[kk][64+ty*4];
            float4 B0 = *(const float4*)&Bs[kk][tx*4];
            float4 B1 = *(const float4*)&Bs[kk][64+tx*4];
            float ar[8]={A0.x,A0.y,A0.z,A0.w,A1.x,A1.y,A1.z,A1.w};
            float br[8]={B0.x,B0.y,B0.z,B0.w,B1.x,B1.y,B1.z,B1.w};
            #pragma unroll
            for (int i=0;i<8;i++)
                #pragma unroll
                for (int j=0;j<8;j++) acc[i][j] += ar[i]*br[j];
        }
        __syncthreads();
    }
    #pragma unroll
    for (int i=0;i<8;i++){
        int r = blockIdx.x*128 + ((i<4)? (ty*4+i) : (64+ty*4+(i-4)));
        float* cp = C + (size_t)r*HH + blockIdx.y*128;
        float4 v0 = make_float4(acc[i][0],acc[i][1],acc[i][2],acc[i][3]);
        float4 v1 = make_float4(acc[i][4],acc[i][5],acc[i][6],acc[i][7]);
        *(float4*)(cp + tx*4)      = v0;
        *(float4*)(cp + 64 + tx*4) = v1;
    }
}

// ---------------- per-node attention logits alpha_s/alpha_d ----------------
__global__ __launch_bounds__(256) void k_alpha(const float* __restrict__ aw_s,
                                               const float* __restrict__ aw_d)
{
    __shared__ float s_s[HH], s_d[HH];
    for (int i=threadIdx.x;i<HH;i+=256){ s_s[i]=aw_s[i]; s_d[i]=aw_d[i]; }
    __syncthreads();
    int wid = threadIdx.x>>5, lane = threadIdx.x&31;
    int row = blockIdx.x*8 + wid;
    if (row >= BATCH*NN) return;
    const float* h = g_H + (size_t)row*HH;
    #pragma unroll
    for (int hh=0; hh<NH; hh++){
        float s=0.f, d=0.f;
        #pragma unroll
        for (int k=lane;k<DOUT;k+=32){
            float hv = h[hh*DOUT+k];
            s += hv*s_s[hh*DOUT+k];
            d += hv*s_d[hh*DOUT+k];
        }
        s = warpSum(s); d = warpSum(d);
        if (lane==0){ g_as[row*NH+hh]=s; g_ad[row*NH+hh]=d; }
    }
}

// ---------------- text dsts: one warp per (b,t), fully fused GAT+ReLU+residual+LN --------
__global__ __launch_bounds__(256) void k_text(int cur, const float* __restrict__ bias,
        const float* __restrict__ gamma, const float* __restrict__ beta,
        float* __restrict__ outp, int isLast)
{
    int gw = blockIdx.x*8 + (threadIdx.x>>5);
    int lane = threadIdx.x & 31;
    if (gw >= BATCH*TT) return;
    int b = gw / TT, t = gw % TT;
    const float* Xcur = g_X[cur];
    float* dst; size_t drow;
    if (isLast){ dst = outp;       drow = ((size_t)b*TT + t)*HH; }
    else       { dst = g_X[cur^1]; drow = ((size_t)b*NN + t)*HH; }

    int el = g_excl[0][b*TT+t], ei = g_excl[1][b*TT+t];
    int srcs[9];
    srcs[0]=t;
    srcs[1]=(t>0)? t-1 : t;
    srcs[2]=(t<TT-1)? t+1 : t;
    srcs[3]=TT + 0 + (0>=el);
    srcs[4]=TT + 1 + (1>=el);
    srcs[5]=TT + 2 + (2>=el);
    srcs[6]=TT+LL + 0 + (0>=ei);
    srcs[7]=TT+LL + 1 + (1>=ei);
    srcs[8]=TT+LL + 2 + (2>=ei);
    bool valid1 = (t>0), valid2 = (t<TT-1);

    size_t nbase = (size_t)b*NN;
    float4 adv = ((const float4*)g_ad)[nbase + t];
    float adh[4] = {adv.x, adv.y, adv.z, adv.w};
    float w[9][4];
    float mx[4] = {-1e30f,-1e30f,-1e30f,-1e30f};
    #pragma unroll
    for (int e=0;e<9;e++){
        float4 av = ((const float4*)g_as)[nbase + srcs[e]];
        float a[4] = {av.x,av.y,av.z,av.w};
        bool v = (e==1)? valid1 : ((e==2)? valid2 : true);
        #pragma unroll
        for (int h=0;h<4;h++){
            float ev = lrelu(a[h] + adh[h]);
            ev = v ? ev : -1e30f;
            w[e][h]=ev;
            mx[h]=fmaxf(mx[h],ev);
        }
    }
    float den[4]={0,0,0,0};
    #pragma unroll
    for (int e=0;e<9;e++)
        #pragma unroll
        for (int h=0;h<4;h++){ float ex=expf(w[e][h]-mx[h]); w[e][h]=ex; den[h]+=ex; }
    #pragma unroll
    for (int h=0;h<4;h++) den[h] = 1.f/(den[h]+1e-16f);
    #pragma unroll
    for (int e=0;e<9;e++)
        #pragma unroll
        for (int h=0;h<4;h++) w[e][h]*=den[h];

    float acc[24];
    #pragma unroll
    for (int i=0;i<24;i++) acc[i]=0.f;
    const float* Hb = g_H + nbase*HH;
    #pragma unroll
    for (int e=0;e<9;e++){
        const float* hr = Hb + (size_t)srcs[e]*HH + lane;
        #pragma unroll
        for (int i=0;i<24;i++) acc[i] += w[e][i/6]*hr[32*i];  // head = i/6 (192 = 6*32)
    }
    // epilogue: ReLU(agg+bias) + x, LayerNorm
    const float* xr = Xcur + (nbase + t)*HH + lane;
    float s=0.f;
    #pragma unroll
    for (int i=0;i<24;i++){
        int c = lane + 32*i;
        float v = fmaxf(acc[i] + bias[c], 0.f) + xr[32*i];
        acc[i]=v; s+=v;
    }
    s = warpSum(s);
    float mean = s*(1.f/HH);
    float q=0.f;
    #pragma unroll
    for (int i=0;i<24;i++){ float dd=acc[i]-mean; q+=dd*dd; }
    q = warpSum(q);
    float rstd = rsqrtf(q*(1.f/HH)+1e-5f);
    #pragma unroll
    for (int i=0;i<24;i++){
        int c = lane+32*i;
        dst[drow + c] = (acc[i]-mean)*rstd*gamma[c] + beta[c];
    }
}

// ---------------- label/image dsts: one block per (b,d), ~390 incoming edges ----------
__global__ __launch_bounds__(256) void k_heavy(int cur, const float* __restrict__ bias,
        const float* __restrict__ gamma, const float* __restrict__ beta)
{
    __shared__ float s_w[TT*NH];       // exp-weights for text srcs (8 KB)
    __shared__ float s_wh[8*NH];       // exp-weights for heavy srcs
    __shared__ float s_red[32];
    __shared__ float s_mx[NH];
    __shared__ float s_den[NH];
    __shared__ float s_adh[NH];
    __shared__ float s_stats[2];

    int bd = blockIdx.x;
    int b = bd >> 3, d = bd & 7;
    int node = TT + d;
    int typ = d >> 2, dl = d & 3;
    int tid = threadIdx.x, wid = tid>>5, lane = tid&31;
    const float* asb = g_as + (size_t)b*NN*NH;
    const int* excl = g_excl[typ] + b*TT;

    if (tid < NH) s_adh[tid] = g_ad[((size_t)b*NN + node)*NH + tid];
    __syncthreads();

    // pass 1: raw logits e -> smem, thread-local max
    float mx0=-1e30f, mx1=-1e30f, mx2=-1e30f, mx3=-1e30f;
    for (int t=tid;t<TT;t+=256){
        bool v = (excl[t] != dl);
        const float* ap = asb + t*NH;
        float e0 = v ? lrelu(ap[0]+s_adh[0]) : -1e30f;
        float e1 = v ? lrelu(ap[1]+s_adh[1]) : -1e30f;
        float e2 = v ? lrelu(ap[2]+s_adh[2]) : -1e30f;
        float e3 = v ? lrelu(ap[3]+s_adh[3]) : -1e30f;
        s_w[t*NH+0]=e0; s_w[t*NH+1]=e1; s_w[t*NH+2]=e2; s_w[t*NH+3]=e3;
        mx0=fmaxf(mx0,e0); mx1=fmaxf(mx1,e1); mx2=fmaxf(mx2,e2); mx3=fmaxf(mx3,e3);
    }
    if (tid < 8){
        const float* ap = asb + (TT+tid)*NH;
        float e0=lrelu(ap[0]+s_adh[0]), e1=lrelu(ap[1]+s_adh[1]);
        float e2=lrelu(ap[2]+s_adh[2]), e3=lrelu(ap[3]+s_adh[3]);
        s_wh[tid*NH+0]=e0; s_wh[tid*NH+1]=e1; s_wh[tid*NH+2]=e2; s_wh[tid*NH+3]=e3;
        mx0=fmaxf(mx0,e0); mx1=fmaxf(mx1,e1); mx2=fmaxf(mx2,e2); mx3=fmaxf(mx3,e3);
    }
    mx0=warpMax(mx0); mx1=warpMax(mx1); mx2=warpMax(mx2); mx3=warpMax(mx3);
    if (lane==0){ s_red[wid*4+0]=mx0; s_red[wid*4+1]=mx1; s_red[wid*4+2]=mx2; s_red[wid*4+3]=mx3; }
    __syncthreads();
    if (tid < 4){
        float m=-1e30f;
        #pragma unroll
        for (int wg=0;wg<8;wg++) m = fmaxf(m, s_red[wg*4+tid]);
        s_mx[tid]=m;
    }
    __syncthreads();

    // pass 2: exp + denominator
    float M0=s_mx[0],M1=s_mx[1],M2=s_mx[2],M3=s_mx[3];
    float dn0=0,dn1=0,dn2=0,dn3=0;
    for (int t=tid;t<TT;t+=256){
        float x0=expf(s_w[t*NH+0]-M0); s_w[t*NH+0]=x0; dn0+=x0;
        float x1=expf(s_w[t*NH+1]-M1); s_w[t*NH+1]=x1; dn1+=x1;
        float x2=expf(s_w[t*NH+2]-M2); s_w[t*NH+2]=x2; dn2+=x2;
        float x3=expf(s_w[t*NH+3]-M3); s_w[t*NH+3]=x3; dn3+=x3;
    }
    if (tid < 8){
        float x0=expf(s_wh[tid*NH+0]-M0); s_wh[tid*NH+0]=x0; dn0+=x0;
        float x1=expf(s_wh[tid*NH+1]-M1); s_wh[tid*NH+1]=x1; dn1+=x1;
        float x2=expf(s_wh[tid*NH+2]-M2); s_wh[tid*NH+2]=x2; dn2+=x2;
        float x3=expf(s_wh[tid*NH+3]-M3); s_wh[tid*NH+3]=x3; dn3+=x3;
    }
    dn0=warpSum(dn0); dn1=warpSum(dn1); dn2=warpSum(dn2); dn3=warpSum(dn3);
    if (lane==0){ s_red[wid*4+0]=dn0; s_red[wid*4+1]=dn1; s_red[wid*4+2]=dn2; s_red[wid*4+3]=dn3; }
    __syncthreads();
    if (tid < 4){
        float sm=0.f;
        #pragma unroll
        for (int wg=0;wg<8;wg++) sm += s_red[wg*4+tid];
        s_den[tid]=sm;
    }
    __syncthreads();

    // pass 3: aggregation over all srcs, columns coalesced (3 cols/thread)
    int c0=tid, c1=tid+256, c2=tid+512;
    int h0=c0/DOUT, h1=c1/DOUT, h2=c2/DOUT;
    const float* Hb = g_H + (size_t)b*NN*HH;
    float a0=0.f, a1=0.f, a2=0.f;
    #pragma unroll 4
    for (int t=0;t<TT;t++){
        const float* hr = Hb + (size_t)t*HH;
        a0 += s_w[t*NH+h0]*hr[c0];
        a1 += s_w[t*NH+h1]*hr[c1];
        a2 += s_w[t*NH+h2]*hr[c2];
    }
    #pragma unroll
    for (int s=0;s<8;s++){
        const float* hr = Hb + (size_t)(TT+s)*HH;
        a0 += s_wh[s*NH+h0]*hr[c0];
        a1 += s_wh[s*NH+h1]*hr[c1];
        a2 += s_wh[s*NH+h2]*hr[c2];
    }
    a0 *= 1.f/(s_den[h0]+1e-16f);
    a1 *= 1.f/(s_den[h1]+1e-16f);
    a2 *= 1.f/(s_den[h2]+1e-16f);

    // epilogue: ReLU(agg+bias)+x, LayerNorm (block-wide)
    size_t row = ((size_t)b*NN + node)*HH;
    const float* xr = g_X[cur] + row;
    float y0 = fmaxf(a0+bias[c0],0.f)+xr[c0];
    float y1 = fmaxf(a1+bias[c1],0.f)+xr[c1];
    float y2 = fmaxf(a2+bias[c2],0.f)+xr[c2];
    float ps = y0+y1+y2;
    float pq = y0*y0+y1*y1+y2*y2;
    ps = warpSum(ps); pq = warpSum(pq);
    if (lane==0){ s_red[wid]=ps; s_red[8+wid]=pq; }
    __syncthreads();
    if (tid==0){
        float S=0.f,Q=0.f;
        #pragma unroll
        for (int wg=0;wg<8;wg++){ S+=s_red[wg]; Q+=s_red[8+wg]; }
        float mean = S*(1.f/HH);
        float var  = Q*(1.f/HH) - mean*mean;
        s_stats[0]=mean;
        s_stats[1]=rsqrtf(fmaxf(var,0.f)+1e-5f);
    }
    __syncthreads();
    float mean=s_stats[0], rstd=s_stats[1];
    float* xd = g_X[cur^1] + row;
    xd[c0] = (y0-mean)*rstd*gamma[c0]+beta[c0];
    xd[c1] = (y1-mean)*rstd*gamma[c1]+beta[c1];
    xd[c2] = (y2-mean)*rstd*gamma[c2]+beta[c2];
}

// ---------------- launch ----------------
extern "C" void kernel_launch(void* const* d_in, const int* in_sizes, int n_in,
                              void* d_out, int out_size)
{
    const float* text = (const float*)d_in[0];
    const float* lab  = (const float*)d_in[1];
    const float* img  = (const float*)d_in[2];
    const float* Ws   = (const float*)d_in[3];
    const float* aws  = (const float*)d_in[4];
    const float* awd  = (const float*)d_in[5];
    const float* bias = (const float*)d_in[6];
    const float* gam  = (const float*)d_in[7];
    const float* bet  = (const float*)d_in[8];
    float* outp = (float*)d_out;

    {
        size_t total = (size_t)BATCH*NN*H4;
        int blocks = (int)((total + 255)/256);
        k_concat<<<blocks,256>>>((const float4*)text,(const float4*)lab,(const float4*)img);
    }
    k_excl<<<BATCH,256>>>(text, lab, img);

    int cur = 0;
    for (int l=0;l<3;l++){
        k_gemm<<<dim3((BATCH*NN)/128, HH/128),256>>>(cur, Ws + (size_t)l*HH*HH);
        k_alpha<<<(BATCH*NN)/8,256>>>(aws + l*HH, awd + l*HH);
        int last = (l==2);
        k_text<<<(BATCH*TT)/8,256>>>(cur, bias+l*HH, gam+l*HH, bet+l*HH, outp, last);
        if (!last) k_heavy<<<BATCH*8,256>>>(cur, bias+l*HH, gam+l*HH, bet+l*HH);
        cur ^= 1;
    }
}

// round 6
// speedup vs baseline: 1.5535x; 1.5535x over previous
#include <cuda_runtime.h>
#include <cuda_bf16.h>
#include <math.h>
#include <stdint.h>

#define BATCH 64
#define TT 512
#define LL 4
#define II 4
#define NN 520          // TT+LL+II
#define HH 768
#define NH 4
#define DOUT 192
#define H4 (HH/4)
#define KCH 36          // 36 K-chunks of 64 (hi,hi,lo x 12)

// ---------------- scratch (device globals; no allocations allowed) ----------------
__device__ float g_X[2][(size_t)BATCH*NN*HH];   // ping-pong node features (fp32 residual path)
__device__ float g_H[(size_t)BATCH*NN*HH];      // h = X @ W^T
__device__ float g_as[BATCH*NN*NH];             // (h*a_s).sum(-1)
__device__ float g_ad[BATCH*NN*NH];             // (h*a_d).sum(-1)
__device__ int   g_excl[2][BATCH*TT];           // [0]=excluded label idx, [1]=excluded image idx
__device__ __nv_bfloat16 g_Ahi[(size_t)BATCH*NN*HH];  // bf16 hi(X)
__device__ __nv_bfloat16 g_Alo[(size_t)BATCH*NN*HH];  // bf16 lo(X)
__device__ __nv_bfloat16 g_Wh[(size_t)3*HH*HH];       // bf16 hi(W)
__device__ __nv_bfloat16 g_Wl[(size_t)3*HH*HH];       // bf16 lo(W)

__device__ __forceinline__ float warpSum(float v){
    #pragma unroll
    for (int o=16;o;o>>=1) v += __shfl_xor_sync(0xffffffffu, v, o);
    return v;
}
__device__ __forceinline__ float warpMax(float v){
    #pragma unroll
    for (int o=16;o;o>>=1) v = fmaxf(v, __shfl_xor_sync(0xffffffffu, v, o));
    return v;
}
__device__ __forceinline__ float lrelu(float x){ return x > 0.f ? x : 0.2f*x; }

__device__ __forceinline__ uint32_t smem_u32(const void* p){
    uint32_t a;
    asm("{ .reg .u64 t; cvta.to.shared.u64 t, %1; cvt.u32.u64 %0, t; }" : "=r"(a) : "l"(p));
    return a;
}
__device__ __forceinline__ __nv_bfloat16 bflo(float x, __nv_bfloat16 h){
    return __float2bfloat16(x - __bfloat162float(h));
}

// ---------------- W -> bf16 hi/lo (once for all layers) ----------------
__global__ void k_wconv(const float* __restrict__ Ws){
    size_t i = (size_t)blockIdx.x*256 + threadIdx.x;
    if (i >= (size_t)3*HH*HH) return;
    float w = Ws[i];
    __nv_bfloat16 h = __float2bfloat16(w);
    g_Wh[i] = h;
    g_Wl[i] = bflo(w, h);
}

// ---------------- concat [text;label;image] -> X0 (+ bf16 hi/lo) ----------------
__global__ void k_concat(const float4* __restrict__ text, const float4* __restrict__ lab,
                         const float4* __restrict__ img)
{
    size_t idx = (size_t)blockIdx.x*blockDim.x + threadIdx.x;
    const size_t total = (size_t)BATCH*NN*H4;
    if (idx >= total) return;
    int b = (int)(idx / (NN*H4));
    int r = (int)(idx % (NN*H4));
    int n = r / H4;
    int k = r % H4;
    float4 v;
    if (n < TT)          v = text[(size_t)b*TT*H4 + (size_t)n*H4 + k];
    else if (n < TT+LL)  v = lab [(size_t)b*LL*H4 + (size_t)(n-TT)*H4 + k];
    else                 v = img [(size_t)b*II*H4 + (size_t)(n-TT-LL)*H4 + k];
    ((float4*)g_X[0])[idx] = v;
    __nv_bfloat16 hx=__float2bfloat16(v.x), hy=__float2bfloat16(v.y);
    __nv_bfloat16 hz=__float2bfloat16(v.z), hw=__float2bfloat16(v.w);
    ((__nv_bfloat162*)g_Ahi)[2*idx]   = __halves2bfloat162(hx,hy);
    ((__nv_bfloat162*)g_Ahi)[2*idx+1] = __halves2bfloat162(hz,hw);
    ((__nv_bfloat162*)g_Alo)[2*idx]   = __halves2bfloat162(bflo(v.x,hx), bflo(v.y,hy));
    ((__nv_bfloat162*)g_Alo)[2*idx+1] = __halves2bfloat162(bflo(v.z,hz), bflo(v.w,hw));
}

// ---------------- dynamic edges ----------------
__global__ void k_excl(const float* __restrict__ text, const float* __restrict__ lab,
                       const float* __restrict__ img)
{
    __shared__ float sh[8*HH];
    __shared__ float sinv[8];
    int b = blockIdx.x;
    int tid = threadIdx.x;
    for (int i=tid;i<LL*HH;i+=blockDim.x) sh[i]       = lab[(size_t)b*LL*HH + i];
    for (int i=tid;i<II*HH;i+=blockDim.x) sh[LL*HH+i] = img[(size_t)b*II*HH + i];
    __syncthreads();
    int wid = tid>>5, lane = tid&31;
    if (wid < 8){
        float s=0.f;
        for (int k=lane;k<HH;k+=32){ float v=sh[wid*HH+k]; s+=v*v; }
        s = warpSum(s);
        if (lane==0) sinv[wid] = 1.f / fmaxf(sqrtf(s), 1e-8f);
    }
    __syncthreads();
    for (int t=wid;t<TT;t+=8){
        const float* xr = text + (size_t)b*TT*HH + (size_t)t*HH;
        float d0=0,d1=0,d2=0,d3=0,d4=0,d5=0,d6=0,d7=0;
        for (int k=lane;k<HH;k+=32){
            float x = xr[k];
            d0+=x*sh[0*HH+k]; d1+=x*sh[1*HH+k]; d2+=x*sh[2*HH+k]; d3+=x*sh[3*HH+k];
            d4+=x*sh[4*HH+k]; d5+=x*sh[5*HH+k]; d6+=x*sh[6*HH+k]; d7+=x*sh[7*HH+k];
        }
        d0=warpSum(d0); d1=warpSum(d1); d2=warpSum(d2); d3=warpSum(d3);
        d4=warpSum(d4); d5=warpSum(d5); d6=warpSum(d6); d7=warpSum(d7);
        if (lane==0){
            float c0=d0*sinv[0], c1=d1*sinv[1], c2=d2*sinv[2], c3=d3*sinv[3];
            int el=0; float bm=c0;
            if (c1<bm){bm=c1;el=1;} if (c2<bm){bm=c2;el=2;} if (c3<bm){bm=c3;el=3;}
            g_excl[0][b*TT+t]=el;
            float e0=d4*sinv[4], e1=d5*sinv[5], e2=d6*sinv[6], e3=d7*sinv[7];
            int ei=0; bm=e0;
            if (e1<bm){bm=e1;ei=1;} if (e2<bm){bm=e2;ei=2;} if (e3<bm){bm=e3;ei=3;}
            g_excl[1][b*TT+t]=ei;
        }
    }
}

// ---------------- mma.sync bf16-split GEMM: g_H = X @ W^T ----------------
// K_big = 2304 (A=[hi,hi,lo], B=[hi,lo,hi]); CTA tile 128x128, BK=64,
// 8 warps (2x4 grid, 64x32 warp tiles), cp.async 2-stage pipeline,
// smem rows padded to 72 bf16 for conflict-free ldmatrix.
#define BK 64
#define LDS 72
#define STG_A (128*LDS*2)            // 18432 B
#define STG   (2*STG_A)              // A+B per stage
#define GSMEM (2*STG)                // 73728 B

__device__ __forceinline__ void cp16(uint32_t dst, const void* src){
    asm volatile("cp.async.cg.shared.global [%0], [%1], 16;" :: "r"(dst), "l"(src));
}

__global__ void __launch_bounds__(256) k_gemm_mma(int layer)
{
    extern __shared__ __align__(16) char dsm[];
    uint32_t smem = smem_u32(dsm);
    int tid = threadIdx.x, lane = tid&31, wid = tid>>5;
    int warp_m = (wid&1)*64;
    int warp_n = (wid>>1)*32;

    const __nv_bfloat16* Wb  = g_Wh + (size_t)layer*HH*HH;
    const __nv_bfloat16* Wlb = g_Wl + (size_t)layer*HH*HH;
    size_t arow0 = (size_t)blockIdx.x*128;
    size_t brow0 = (size_t)blockIdx.y*128;

    int lr = tid>>1;            // 0..127 (load row)
    int lq = (tid&1)<<2;        // 0 or 4 (uint4 index base; 2 uint4 per thread x2? no:)
    // loads: 128 rows x 8 uint4 = 1024 per tile; 256 thr -> 4 each: idx = tid + i*256
    float acc[4][4][4];
    #pragma unroll
    for (int mi=0;mi<4;mi++)
        #pragma unroll
        for (int nj=0;nj<4;nj++)
            #pragma unroll
            for (int r=0;r<4;r++) acc[mi][nj][r]=0.f;

    (void)lr; (void)lq;

    // ---- issue loads for chunk c into stage s ----
    auto issue = [&](int c, int s){
        const __nv_bfloat16* Asrc = (c<24)? g_Ahi : g_Alo;
        const __nv_bfloat16* Bsrc = (c<12)? Wb : ((c<24)? Wlb : Wb);
        int col = (c%12)*BK;
        uint32_t sa = smem + s*STG;
        uint32_t sbm = smem + s*STG + STG_A;
        #pragma unroll
        for (int i=0;i<4;i++){
            int idx = tid + i*256;
            int r = idx>>3, q = idx&7;
            cp16(sa + (uint32_t)(r*LDS + q*8)*2,
                 Asrc + (arow0 + r)*HH + col + q*8);
        }
        #pragma unroll
        for (int i=0;i<4;i++){
            int idx = tid + i*256;
            int r = idx>>3, q = idx&7;
            cp16(sbm + (uint32_t)(r*LDS + q*8)*2,
                 Bsrc + (brow0 + r)*HH + col + q*8);
        }
        asm volatile("cp.async.commit_group;" ::: "memory");
    };

    issue(0, 0);

    for (int c=0;c<KCH;c++){
        int s = c&1;
        if (c+1 < KCH){
            issue(c+1, s^1);
            asm volatile("cp.async.wait_group 1;" ::: "memory");
        } else {
            asm volatile("cp.async.wait_group 0;" ::: "memory");
        }
        __syncthreads();

        uint32_t saA = smem + s*STG;
        uint32_t saB = smem + s*STG + STG_A;
        #pragma unroll
        for (int ks=0;ks<4;ks++){
            int kb = ks*16;
            uint32_t aF[4][4];
            uint32_t bF[4][2];
            #pragma unroll
            for (int mi=0;mi<4;mi++){
                int row = warp_m + mi*16 + (lane&15);
                int col = kb + ((lane>>4)<<3);
                uint32_t ad = saA + (uint32_t)(row*LDS + col)*2;
                asm volatile("ldmatrix.sync.aligned.m8n8.x4.shared.b16 {%0,%1,%2,%3}, [%4];"
                    : "=r"(aF[mi][0]), "=r"(aF[mi][1]), "=r"(aF[mi][2]), "=r"(aF[mi][3])
                    : "r"(ad));
            }
            #pragma unroll
            for (int ng=0;ng<2;ng++){
                int n = warp_n + ng*16 + (lane&7) + ((lane>>4)<<3);
                int k = kb + (((lane>>3)&1)<<3);
                uint32_t ad = saB + (uint32_t)(n*LDS + k)*2;
                uint32_t r0,r1,r2,r3;
                asm volatile("ldmatrix.sync.aligned.m8n8.x4.shared.b16 {%0,%1,%2,%3}, [%4];"
                    : "=r"(r0), "=r"(r1), "=r"(r2), "=r"(r3) : "r"(ad));
                bF[ng*2+0][0]=r0; bF[ng*2+0][1]=r1;
                bF[ng*2+1][0]=r2; bF[ng*2+1][1]=r3;
            }
            #pragma unroll
            for (int mi=0;mi<4;mi++)
                #pragma unroll
                for (int nj=0;nj<4;nj++){
                    asm volatile(
                        "mma.sync.aligned.m16n8k16.row.col.f32.bf16.bf16.f32 "
                        "{%0,%1,%2,%3}, {%4,%5,%6,%7}, {%8,%9}, {%0,%1,%2,%3};"
                        : "+f"(acc[mi][nj][0]), "+f"(acc[mi][nj][1]),
                          "+f"(acc[mi][nj][2]), "+f"(acc[mi][nj][3])
                        : "r"(aF[mi][0]), "r"(aF[mi][1]), "r"(aF[mi][2]), "r"(aF[mi][3]),
                          "r"(bF[nj][0]), "r"(bF[nj][1]));
                }
        }
        __syncthreads();
    }

    // epilogue: C fragments -> g_H (fp32)
    int g = lane>>2, t2 = (lane&3)*2;
    #pragma unroll
    for (int mi=0;mi<4;mi++){
        size_t row = arow0 + warp_m + mi*16 + g;
        float* cr0 = g_H + row*HH + brow0 + warp_n;
        float* cr1 = g_H + (row+8)*HH + brow0 + warp_n;
        #pragma unroll
        for (int nj=0;nj<4;nj++){
            int col = nj*8 + t2;
            *(float2*)(cr0 + col) = make_float2(acc[mi][nj][0], acc[mi][nj][1]);
            *(float2*)(cr1 + col) = make_float2(acc[mi][nj][2], acc[mi][nj][3]);
        }
    }
}

// ---------------- per-node attention logits alpha_s/alpha_d ----------------
__global__ void __launch_bounds__(256) k_alpha(const float* __restrict__ aw_s,
                                               const float* __restrict__ aw_d)
{
    __shared__ float s_s[HH], s_d[HH];
    for (int i=threadIdx.x;i<HH;i+=256){ s_s[i]=aw_s[i]; s_d[i]=aw_d[i]; }
    __syncthreads();
    int wid = threadIdx.x>>5, lane = threadIdx.x&31;
    int row = blockIdx.x*8 + wid;
    if (row >= BATCH*NN) return;
    const float* h = g_H + (size_t)row*HH;
    #pragma unroll
    for (int hh=0; hh<NH; hh++){
        float s=0.f, d=0.f;
        #pragma unroll
        for (int k=lane;k<DOUT;k+=32){
            float hv = h[hh*DOUT+k];
            s += hv*s_s[hh*DOUT+k];
            d += hv*s_d[hh*DOUT+k];
        }
        s = warpSum(s); d = warpSum(d);
        if (lane==0){ g_as[row*NH+hh]=s; g_ad[row*NH+hh]=d; }
    }
}

// ---------------- text dsts: one warp per (b,t) ----------------
__global__ void __launch_bounds__(256) k_text(int cur, const float* __restrict__ bias,
        const float* __restrict__ gamma, const float* __restrict__ beta,
        float* __restrict__ outp, int isLast)
{
    int gw = blockIdx.x*8 + (threadIdx.x>>5);
    int lane = threadIdx.x & 31;
    if (gw >= BATCH*TT) return;
    int b = gw / TT, t = gw % TT;
    const float* Xcur = g_X[cur];
    float* dst; size_t drow;
    if (isLast){ dst = outp;       drow = ((size_t)b*TT + t)*HH; }
    else       { dst = g_X[cur^1]; drow = ((size_t)b*NN + t)*HH; }

    int el = g_excl[0][b*TT+t], ei = g_excl[1][b*TT+t];
    int srcs[9];
    srcs[0]=t;
    srcs[1]=(t>0)? t-1 : t;
    srcs[2]=(t<TT-1)? t+1 : t;
    srcs[3]=TT + 0 + (0>=el);
    srcs[4]=TT + 1 + (1>=el);
    srcs[5]=TT + 2 + (2>=el);
    srcs[6]=TT+LL + 0 + (0>=ei);
    srcs[7]=TT+LL + 1 + (1>=ei);
    srcs[8]=TT+LL + 2 + (2>=ei);
    bool valid1 = (t>0), valid2 = (t<TT-1);

    size_t nbase = (size_t)b*NN;
    float4 adv = ((const float4*)g_ad)[nbase + t];
    float adh[4] = {adv.x, adv.y, adv.z, adv.w};
    float w[9][4];
    float mx[4] = {-1e30f,-1e30f,-1e30f,-1e30f};
    #pragma unroll
    for (int e=0;e<9;e++){
        float4 av = ((const float4*)g_as)[nbase + srcs[e]];
        float a[4] = {av.x,av.y,av.z,av.w};
        bool v = (e==1)? valid1 : ((e==2)? valid2 : true);
        #pragma unroll
        for (int h=0;h<4;h++){
            float ev = lrelu(a[h] + adh[h]);
            ev = v ? ev : -1e30f;
            w[e][h]=ev;
            mx[h]=fmaxf(mx[h],ev);
        }
    }
    float den[4]={0,0,0,0};
    #pragma unroll
    for (int e=0;e<9;e++)
        #pragma unroll
        for (int h=0;h<4;h++){ float ex=expf(w[e][h]-mx[h]); w[e][h]=ex; den[h]+=ex; }
    #pragma unroll
    for (int h=0;h<4;h++) den[h] = 1.f/(den[h]+1e-16f);
    #pragma unroll
    for (int e=0;e<9;e++)
        #pragma unroll
        for (int h=0;h<4;h++) w[e][h]*=den[h];

    float acc[24];
    #pragma unroll
    for (int i=0;i<24;i++) acc[i]=0.f;
    const float* Hb = g_H + nbase*HH;
    #pragma unroll
    for (int e=0;e<9;e++){
        const float* hr = Hb + (size_t)srcs[e]*HH + lane;
        #pragma unroll
        for (int i=0;i<24;i++) acc[i] += w[e][i/6]*hr[32*i];
    }
    const float* xr = Xcur + (nbase + t)*HH + lane;
    float s=0.f;
    #pragma unroll
    for (int i=0;i<24;i++){
        int c = lane + 32*i;
        float v = fmaxf(acc[i] + bias[c], 0.f) + xr[32*i];
        acc[i]=v; s+=v;
    }
    s = warpSum(s);
    float mean = s*(1.f/HH);
    float q=0.f;
    #pragma unroll
    for (int i=0;i<24;i++){ float dd=acc[i]-mean; q+=dd*dd; }
    q = warpSum(q);
    float rstd = rsqrtf(q*(1.f/HH)+1e-5f);
    if (isLast){
        #pragma unroll
        for (int i=0;i<24;i++){
            int c = lane+32*i;
            dst[drow + c] = (acc[i]-mean)*rstd*gamma[c] + beta[c];
        }
    } else {
        #pragma unroll
        for (int i=0;i<24;i++){
            int c = lane+32*i;
            float o = (acc[i]-mean)*rstd*gamma[c] + beta[c];
            dst[drow + c] = o;
            __nv_bfloat16 h = __float2bfloat16(o);
            g_Ahi[drow + c] = h;
            g_Alo[drow + c] = bflo(o, h);
        }
    }
}

// ---------------- label/image dsts: one block per (b,d) ----------
__global__ void __launch_bounds__(256) k_heavy(int cur, const float* __restrict__ bias,
        const float* __restrict__ gamma, const float* __restrict__ beta)
{
    __shared__ float s_w[TT*NH];
    __shared__ float s_wh[8*NH];
    __shared__ float s_red[32];
    __shared__ float s_mx[NH];
    __shared__ float s_den[NH];
    __shared__ float s_adh[NH];
    __shared__ float s_stats[2];

    int bd = blockIdx.x;
    int b = bd >> 3, d = bd & 7;
    int node = TT + d;
    int typ = d >> 2, dl = d & 3;
    int tid = threadIdx.x, wid = tid>>5, lane = tid&31;
    const float* asb = g_as + (size_t)b*NN*NH;
    const int* excl = g_excl[typ] + b*TT;

    if (tid < NH) s_adh[tid] = g_ad[((size_t)b*NN + node)*NH + tid];
    __syncthreads();

    float mx0=-1e30f, mx1=-1e30f, mx2=-1e30f, mx3=-1e30f;
    for (int t=tid;t<TT;t+=256){
        bool v = (excl[t] != dl);
        const float* ap = asb + t*NH;
        float e0 = v ? lrelu(ap[0]+s_adh[0]) : -1e30f;
        float e1 = v ? lrelu(ap[1]+s_adh[1]) : -1e30f;
        float e2 = v ? lrelu(ap[2]+s_adh[2]) : -1e30f;
        float e3 = v ? lrelu(ap[3]+s_adh[3]) : -1e30f;
        s_w[t*NH+0]=e0; s_w[t*NH+1]=e1; s_w[t*NH+2]=e2; s_w[t*NH+3]=e3;
        mx0=fmaxf(mx0,e0); mx1=fmaxf(mx1,e1); mx2=fmaxf(mx2,e2); mx3=fmaxf(mx3,e3);
    }
    if (tid < 8){
        const float* ap = asb + (TT+tid)*NH;
        float e0=lrelu(ap[0]+s_adh[0]), e1=lrelu(ap[1]+s_adh[1]);
        float e2=lrelu(ap[2]+s_adh[2]), e3=lrelu(ap[3]+s_adh[3]);
        s_wh[tid*NH+0]=e0; s_wh[tid*NH+1]=e1; s_wh[tid*NH+2]=e2; s_wh[tid*NH+3]=e3;
        mx0=fmaxf(mx0,e0); mx1=fmaxf(mx1,e1); mx2=fmaxf(mx2,e2); mx3=fmaxf(mx3,e3);
    }
    mx0=warpMax(mx0); mx1=warpMax(mx1); mx2=warpMax(mx2); mx3=warpMax(mx3);
    if (lane==0){ s_red[wid*4+0]=mx0; s_red[wid*4+1]=mx1; s_red[wid*4+2]=mx2; s_red[wid*4+3]=mx3; }
    __syncthreads();
    if (tid < 4){
        float m=-1e30f;
        #pragma unroll
        for (int wg=0;wg<8;wg++) m = fmaxf(m, s_red[wg*4+tid]);
        s_mx[tid]=m;
    }
    __syncthreads();

    float M0=s_mx[0],M1=s_mx[1],M2=s_mx[2],M3=s_mx[3];
    float dn0=0,dn1=0,dn2=0,dn3=0;
    for (int t=tid;t<TT;t+=256){
        float x0=expf(s_w[t*NH+0]-M0); s_w[t*NH+0]=x0; dn0+=x0;
        float x1=expf(s_w[t*NH+1]-M1); s_w[t*NH+1]=x1; dn1+=x1;
        float x2=expf(s_w[t*NH+2]-M2); s_w[t*NH+2]=x2; dn2+=x2;
        float x3=expf(s_w[t*NH+3]-M3); s_w[t*NH+3]=x3; dn3+=x3;
    }
    if (tid < 8){
        float x0=expf(s_wh[tid*NH+0]-M0); s_wh[tid*NH+0]=x0; dn0+=x0;
        float x1=expf(s_wh[tid*NH+1]-M1); s_wh[tid*NH+1]=x1; dn1+=x1;
        float x2=expf(s_wh[tid*NH+2]-M2); s_wh[tid*NH+2]=x2; dn2+=x2;
        float x3=expf(s_wh[tid*NH+3]-M3); s_wh[tid*NH+3]=x3; dn3+=x3;
    }
    dn0=warpSum(dn0); dn1=warpSum(dn1); dn2=warpSum(dn2); dn3=warpSum(dn3);
    if (lane==0){ s_red[wid*4+0]=dn0; s_red[wid*4+1]=dn1; s_red[wid*4+2]=dn2; s_red[wid*4+3]=dn3; }
    __syncthreads();
    if (tid < 4){
        float sm=0.f;
        #pragma unroll
        for (int wg=0;wg<8;wg++) sm += s_red[wg*4+tid];
        s_den[tid]=sm;
    }
    __syncthreads();

    int c0=tid, c1=tid+256, c2=tid+512;
    int h0=c0/DOUT, h1=c1/DOUT, h2=c2/DOUT;
    const float* Hb = g_H + (size_t)b*NN*HH;
    float a0=0.f, a1=0.f, a2=0.f;
    #pragma unroll 4
    for (int t=0;t<TT;t++){
        const float* hr = Hb + (size_t)t*HH;
        a0 += s_w[t*NH+h0]*hr[c0];
        a1 += s_w[t*NH+h1]*hr[c1];
        a2 += s_w[t*NH+h2]*hr[c2];
    }
    #pragma unroll
    for (int s=0;s<8;s++){
        const float* hr = Hb + (size_t)(TT+s)*HH;
        a0 += s_wh[s*NH+h0]*hr[c0];
        a1 += s_wh[s*NH+h1]*hr[c1];
        a2 += s_wh[s*NH+h2]*hr[c2];
    }
    a0 *= 1.f/(s_den[h0]+1e-16f);
    a1 *= 1.f/(s_den[h1]+1e-16f);
    a2 *= 1.f/(s_den[h2]+1e-16f);

    size_t row = ((size_t)b*NN + node)*HH;
    const float* xr = g_X[cur] + row;
    float y0 = fmaxf(a0+bias[c0],0.f)+xr[c0];
    float y1 = fmaxf(a1+bias[c1],0.f)+xr[c1];
    float y2 = fmaxf(a2+bias[c2],0.f)+xr[c2];
    float ps = y0+y1+y2;
    float pq = y0*y0+y1*y1+y2*y2;
    ps = warpSum(ps); pq = warpSum(pq);
    if (lane==0){ s_red[wid]=ps; s_red[8+wid]=pq; }
    __syncthreads();
    if (tid==0){
        float S=0.f,Q=0.f;
        #pragma unroll
        for (int wg=0;wg<8;wg++){ S+=s_red[wg]; Q+=s_red[8+wg]; }
        float mean = S*(1.f/HH);
        float var  = Q*(1.f/HH) - mean*mean;
        s_stats[0]=mean;
        s_stats[1]=rsqrtf(fmaxf(var,0.f)+1e-5f);
    }
    __syncthreads();
    float mean=s_stats[0], rstd=s_stats[1];
    float* xd = g_X[cur^1] + row;
    float o0 = (y0-mean)*rstd*gamma[c0]+beta[c0];
    float o1 = (y1-mean)*rstd*gamma[c1]+beta[c1];
    float o2 = (y2-mean)*rstd*gamma[c2]+beta[c2];
    xd[c0]=o0; xd[c1]=o1; xd[c2]=o2;
    __nv_bfloat16 b0h=__float2bfloat16(o0), b1h=__float2bfloat16(o1), b2h=__float2bfloat16(o2);
    g_Ahi[row+c0]=b0h; g_Ahi[row+c1]=b1h; g_Ahi[row+c2]=b2h;
    g_Alo[row+c0]=bflo(o0,b0h); g_Alo[row+c1]=bflo(o1,b1h); g_Alo[row+c2]=bflo(o2,b2h);
}

// ---------------- launch ----------------
extern "C" void kernel_launch(void* const* d_in, const int* in_sizes, int n_in,
                              void* d_out, int out_size)
{
    const float* text = (const float*)d_in[0];
    const float* lab  = (const float*)d_in[1];
    const float* img  = (const float*)d_in[2];
    const float* Ws   = (const float*)d_in[3];
    const float* aws  = (const float*)d_in[4];
    const float* awd  = (const float*)d_in[5];
    const float* bias = (const float*)d_in[6];
    const float* gam  = (const float*)d_in[7];
    const float* bet  = (const float*)d_in[8];
    float* outp = (float*)d_out;

    cudaFuncSetAttribute(k_gemm_mma, cudaFuncAttributeMaxDynamicSharedMemorySize, GSMEM);

    k_wconv<<<(3*HH*HH + 255)/256, 256>>>(Ws);
    {
        size_t total = (size_t)BATCH*NN*H4;
        int blocks = (int)((total + 255)/256);
        k_concat<<<blocks,256>>>((const float4*)text,(const float4*)lab,(const float4*)img);
    }
    k_excl<<<BATCH,256>>>(text, lab, img);

    int cur = 0;
    for (int l=0;l<3;l++){
        k_gemm_mma<<<dim3((BATCH*NN)/128, HH/128), 256, GSMEM>>>(l);
        k_alpha<<<(BATCH*NN)/8,256>>>(aws + l*HH, awd + l*HH);
        int last = (l==2);
        k_text<<<(BATCH*TT)/8,256>>>(cur, bias+l*HH, gam+l*HH, bet+l*HH, outp, last);
        if (!last) k_heavy<<<BATCH*8,256>>>(cur, bias+l*HH, gam+l*HH, bet+l*HH);
        cur ^= 1;
    }
}

// round 7
// speedup vs baseline: 1.6009x; 1.0306x over previous
#include <cuda_runtime.h>
#include <cuda_bf16.h>
#include <math.h>
#include <stdint.h>

#define BATCH 64
#define TT 512
#define LL 4
#define II 4
#define NN 520          // TT+LL+II
#define HH 768
#define NH 4
#define DOUT 192
#define H4 (HH/4)
#define KCH 36          // 36 K-chunks of 64 (hi,hi,lo x 12)

// ---------------- scratch (device globals; no allocations allowed) ----------------
__device__ float g_X[2][(size_t)BATCH*NN*HH];   // ping-pong node features (fp32 residual path)
__device__ float g_H[(size_t)BATCH*NN*HH];      // h = X @ W^T
__device__ float g_as[BATCH*NN*NH];             // (h*a_s).sum(-1)
__device__ float g_ad[BATCH*NN*NH];             // (h*a_d).sum(-1)
__device__ int   g_excl[2][BATCH*TT];           // [0]=excluded label idx, [1]=excluded image idx
__device__ __nv_bfloat16 g_Ahi[(size_t)BATCH*NN*HH];  // bf16 hi(X)
__device__ __nv_bfloat16 g_Alo[(size_t)BATCH*NN*HH];  // bf16 lo(X)
__device__ __nv_bfloat16 g_Wh[(size_t)3*HH*HH];       // bf16 hi(W)
__device__ __nv_bfloat16 g_Wl[(size_t)3*HH*HH];       // bf16 lo(W)

__device__ __forceinline__ float warpSum(float v){
    #pragma unroll
    for (int o=16;o;o>>=1) v += __shfl_xor_sync(0xffffffffu, v, o);
    return v;
}
__device__ __forceinline__ float warpMax(float v){
    #pragma unroll
    for (int o=16;o;o>>=1) v = fmaxf(v, __shfl_xor_sync(0xffffffffu, v, o));
    return v;
}
__device__ __forceinline__ float lrelu(float x){ return x > 0.f ? x : 0.2f*x; }

__device__ __forceinline__ uint32_t smem_u32(const void* p){
    uint32_t a;
    asm("{ .reg .u64 t; cvta.to.shared.u64 t, %1; cvt.u32.u64 %0, t; }" : "=r"(a) : "l"(p));
    return a;
}
__device__ __forceinline__ __nv_bfloat16 bflo(float x, __nv_bfloat16 h){
    return __float2bfloat16(x - __bfloat162float(h));
}

// ---------------- W -> bf16 hi/lo ----------------
__global__ void k_wconv(const float* __restrict__ Ws){
    size_t i = (size_t)blockIdx.x*256 + threadIdx.x;
    if (i >= (size_t)3*HH*HH) return;
    float w = Ws[i];
    __nv_bfloat16 h = __float2bfloat16(w);
    g_Wh[i] = h;
    g_Wl[i] = bflo(w, h);
}

// ---------------- concat [text;label;image] -> X0 (+ bf16 hi/lo) ----------------
__global__ void k_concat(const float4* __restrict__ text, const float4* __restrict__ lab,
                         const float4* __restrict__ img)
{
    size_t idx = (size_t)blockIdx.x*blockDim.x + threadIdx.x;
    const size_t total = (size_t)BATCH*NN*H4;
    if (idx >= total) return;
    int b = (int)(idx / (NN*H4));
    int r = (int)(idx % (NN*H4));
    int n = r / H4;
    int k = r % H4;
    float4 v;
    if (n < TT)          v = text[(size_t)b*TT*H4 + (size_t)n*H4 + k];
    else if (n < TT+LL)  v = lab [(size_t)b*LL*H4 + (size_t)(n-TT)*H4 + k];
    else                 v = img [(size_t)b*II*H4 + (size_t)(n-TT-LL)*H4 + k];
    ((float4*)g_X[0])[idx] = v;
    __nv_bfloat16 hx=__float2bfloat16(v.x), hy=__float2bfloat16(v.y);
    __nv_bfloat16 hz=__float2bfloat16(v.z), hw=__float2bfloat16(v.w);
    ((__nv_bfloat162*)g_Ahi)[2*idx]   = __halves2bfloat162(hx,hy);
    ((__nv_bfloat162*)g_Ahi)[2*idx+1] = __halves2bfloat162(hz,hw);
    ((__nv_bfloat162*)g_Alo)[2*idx]   = __halves2bfloat162(bflo(v.x,hx), bflo(v.y,hy));
    ((__nv_bfloat162*)g_Alo)[2*idx+1] = __halves2bfloat162(bflo(v.z,hz), bflo(v.w,hw));
}

// ---------------- dynamic edges ----------------
__global__ void k_excl(const float* __restrict__ text, const float* __restrict__ lab,
                       const float* __restrict__ img)
{
    __shared__ float sh[8*HH];
    __shared__ float sinv[8];
    int b = blockIdx.x;
    int tid = threadIdx.x;
    for (int i=tid;i<LL*HH;i+=blockDim.x) sh[i]       = lab[(size_t)b*LL*HH + i];
    for (int i=tid;i<II*HH;i+=blockDim.x) sh[LL*HH+i] = img[(size_t)b*II*HH + i];
    __syncthreads();
    int wid = tid>>5, lane = tid&31;
    if (wid < 8){
        float s=0.f;
        for (int k=lane;k<HH;k+=32){ float v=sh[wid*HH+k]; s+=v*v; }
        s = warpSum(s);
        if (lane==0) sinv[wid] = 1.f / fmaxf(sqrtf(s), 1e-8f);
    }
    __syncthreads();
    for (int t=wid;t<TT;t+=8){
        const float* xr = text + (size_t)b*TT*HH + (size_t)t*HH;
        float d0=0,d1=0,d2=0,d3=0,d4=0,d5=0,d6=0,d7=0;
        for (int k=lane;k<HH;k+=32){
            float x = xr[k];
            d0+=x*sh[0*HH+k]; d1+=x*sh[1*HH+k]; d2+=x*sh[2*HH+k]; d3+=x*sh[3*HH+k];
            d4+=x*sh[4*HH+k]; d5+=x*sh[5*HH+k]; d6+=x*sh[6*HH+k]; d7+=x*sh[7*HH+k];
        }
        d0=warpSum(d0); d1=warpSum(d1); d2=warpSum(d2); d3=warpSum(d3);
        d4=warpSum(d4); d5=warpSum(d5); d6=warpSum(d6); d7=warpSum(d7);
        if (lane==0){
            float c0=d0*sinv[0], c1=d1*sinv[1], c2=d2*sinv[2], c3=d3*sinv[3];
            int el=0; float bm=c0;
            if (c1<bm){bm=c1;el=1;} if (c2<bm){bm=c2;el=2;} if (c3<bm){bm=c3;el=3;}
            g_excl[0][b*TT+t]=el;
            float e0=d4*sinv[4], e1=d5*sinv[5], e2=d6*sinv[6], e3=d7*sinv[7];
            int ei=0; bm=e0;
            if (e1<bm){bm=e1;ei=1;} if (e2<bm){bm=e2;ei=2;} if (e3<bm){bm=e3;ei=3;}
            g_excl[1][b*TT+t]=ei;
        }
    }
}

// ---------------- mma.sync bf16-split GEMM: g_H = X @ W^T ----------------
// CTA tile 128x256, BK=64, 8 warps (2x4, 64x64 warp tiles), 3-stage cp.async.
#define BK 64
#define LDSM 72
#define STG_A (128*LDSM*2)            // 18432
#define STG_B (256*LDSM*2)            // 36864
#define STG   (STG_A+STG_B)           // 55296
#define GSMEM (3*STG)                 // 165888

__device__ __forceinline__ void cp16(uint32_t dst, const void* src){
    asm volatile("cp.async.cg.shared.global [%0], [%1], 16;" :: "r"(dst), "l"(src));
}

__global__ void __launch_bounds__(256,1) k_gemm_mma(int layer)
{
    extern __shared__ __align__(16) char dsm[];
    uint32_t smem = smem_u32(dsm);
    int tid = threadIdx.x, lane = tid&31, wid = tid>>5;
    int warp_m = (wid&1)*64;
    int warp_n = (wid>>1)*64;

    const __nv_bfloat16* Wb  = g_Wh + (size_t)layer*HH*HH;
    const __nv_bfloat16* Wlb = g_Wl + (size_t)layer*HH*HH;
    size_t arow0 = (size_t)blockIdx.x*128;
    size_t brow0 = (size_t)blockIdx.y*256;

    float acc[4][8][4];
    #pragma unroll
    for (int mi=0;mi<4;mi++)
        #pragma unroll
        for (int nj=0;nj<8;nj++)
            #pragma unroll
            for (int r=0;r<4;r++) acc[mi][nj][r]=0.f;

    auto issue = [&](int c, int s){
        const __nv_bfloat16* Asrc = (c<24)? g_Ahi : g_Alo;
        const __nv_bfloat16* Bsrc = (c<12)? Wb : ((c<24)? Wlb : Wb);
        int col = (c%12)*BK;
        uint32_t sa  = smem + s*STG;
        uint32_t sbm = smem + s*STG + STG_A;
        #pragma unroll
        for (int i=0;i<4;i++){                 // A: 128 rows x 8 uint4
            int idx = tid + i*256;
            int r = idx>>3, q = idx&7;
            cp16(sa + (uint32_t)(r*LDSM + q*8)*2,
                 Asrc + (arow0 + r)*HH + col + q*8);
        }
        #pragma unroll
        for (int i=0;i<8;i++){                 // B: 256 rows x 8 uint4
            int idx = tid + i*256;
            int r = idx>>3, q = idx&7;
            cp16(sbm + (uint32_t)(r*LDSM + q*8)*2,
                 Bsrc + (brow0 + r)*HH + col + q*8);
        }
        asm volatile("cp.async.commit_group;" ::: "memory");
    };

    issue(0,0);
    issue(1,1);

    for (int c=0;c<KCH;c++){
        int s = c%3;
        if (c+2 < KCH){
            issue(c+2, (c+2)%3);
            asm volatile("cp.async.wait_group 2;" ::: "memory");
        } else if (c+1 < KCH){
            asm volatile("cp.async.wait_group 1;" ::: "memory");
        } else {
            asm volatile("cp.async.wait_group 0;" ::: "memory");
        }
        __syncthreads();

        uint32_t saA = smem + s*STG;
        uint32_t saB = smem + s*STG + STG_A;
        #pragma unroll
        for (int ks=0;ks<4;ks++){
            int kb = ks*16;
            uint32_t aF[4][4];
            uint32_t bF[8][2];
            #pragma unroll
            for (int mi=0;mi<4;mi++){
                int row = warp_m + mi*16 + (lane&15);
                int col = kb + ((lane>>4)<<3);
                uint32_t ad = saA + (uint32_t)(row*LDSM + col)*2;
                asm volatile("ldmatrix.sync.aligned.m8n8.x4.shared.b16 {%0,%1,%2,%3}, [%4];"
                    : "=r"(aF[mi][0]), "=r"(aF[mi][1]), "=r"(aF[mi][2]), "=r"(aF[mi][3])
                    : "r"(ad));
            }
            #pragma unroll
            for (int ng=0;ng<4;ng++){
                int n = warp_n + ng*16 + (lane&7) + ((lane>>4)<<3);
                int k = kb + (((lane>>3)&1)<<3);
                uint32_t ad = saB + (uint32_t)(n*LDSM + k)*2;
                uint32_t r0,r1,r2,r3;
                asm volatile("ldmatrix.sync.aligned.m8n8.x4.shared.b16 {%0,%1,%2,%3}, [%4];"
                    : "=r"(r0), "=r"(r1), "=r"(r2), "=r"(r3) : "r"(ad));
                bF[ng*2+0][0]=r0; bF[ng*2+0][1]=r1;
                bF[ng*2+1][0]=r2; bF[ng*2+1][1]=r3;
            }
            #pragma unroll
            for (int mi=0;mi<4;mi++)
                #pragma unroll
                for (int nj=0;nj<8;nj++){
                    asm volatile(
                        "mma.sync.aligned.m16n8k16.row.col.f32.bf16.bf16.f32 "
                        "{%0,%1,%2,%3}, {%4,%5,%6,%7}, {%8,%9}, {%0,%1,%2,%3};"
                        : "+f"(acc[mi][nj][0]), "+f"(acc[mi][nj][1]),
                          "+f"(acc[mi][nj][2]), "+f"(acc[mi][nj][3])
                        : "r"(aF[mi][0]), "r"(aF[mi][1]), "r"(aF[mi][2]), "r"(aF[mi][3]),
                          "r"(bF[nj][0]), "r"(bF[nj][1]));
                }
        }
        __syncthreads();
    }

    // epilogue
    int g = lane>>2, t2 = (lane&3)*2;
    #pragma unroll
    for (int mi=0;mi<4;mi++){
        size_t row = arow0 + warp_m + mi*16 + g;
        float* cr0 = g_H + row*HH + brow0 + warp_n;
        float* cr1 = g_H + (row+8)*HH + brow0 + warp_n;
        #pragma unroll
        for (int nj=0;nj<8;nj++){
            int col = nj*8 + t2;
            *(float2*)(cr0 + col) = make_float2(acc[mi][nj][0], acc[mi][nj][1]);
            *(float2*)(cr1 + col) = make_float2(acc[mi][nj][2], acc[mi][nj][3]);
        }
    }
}

// ---------------- per-node attention logits alpha_s/alpha_d ----------------
__global__ void __launch_bounds__(256) k_alpha(const float* __restrict__ aw_s,
                                               const float* __restrict__ aw_d)
{
    __shared__ float s_s[HH], s_d[HH];
    for (int i=threadIdx.x;i<HH;i+=256){ s_s[i]=aw_s[i]; s_d[i]=aw_d[i]; }
    __syncthreads();
    int wid = threadIdx.x>>5, lane = threadIdx.x&31;
    int row = blockIdx.x*8 + wid;
    if (row >= BATCH*NN) return;
    const float* h = g_H + (size_t)row*HH;
    #pragma unroll
    for (int hh=0; hh<NH; hh++){
        float s=0.f, d=0.f;
        #pragma unroll
        for (int k=lane;k<DOUT;k+=32){
            float hv = h[hh*DOUT+k];
            s += hv*s_s[hh*DOUT+k];
            d += hv*s_d[hh*DOUT+k];
        }
        s = warpSum(s); d = warpSum(d);
        if (lane==0){ g_as[row*NH+hh]=s; g_ad[row*NH+hh]=d; }
    }
}

// ---------------- text dsts: one warp per (b,t); heavy rows staged in smem ----------
__global__ void __launch_bounds__(256) k_text(int cur, const float* __restrict__ bias,
        const float* __restrict__ gamma, const float* __restrict__ beta,
        float* __restrict__ outp, int isLast)
{
    __shared__ float s_h[8*HH];    // 8 heavy H rows (24KB)
    __shared__ float s_as[32];     // heavy as values
    int tid = threadIdx.x;
    int lane = tid & 31;
    int b = blockIdx.x >> 6;       // 64 blocks per batch
    size_t nbase = (size_t)b*NN;

    {
        const float4* hs = (const float4*)(g_H + (nbase + TT)*HH);
        #pragma unroll
        for (int i=0;i<6;i++) ((float4*)s_h)[tid + i*256] = hs[tid + i*256];
        if (tid < 32) s_as[tid] = g_as[(nbase + TT)*NH + tid];
    }
    __syncthreads();

    int gw = blockIdx.x*8 + (tid>>5);
    int t = gw % TT;
    const float* Xcur = g_X[cur];
    float* dst; size_t drow;
    if (isLast){ dst = outp;       drow = ((size_t)b*TT + t)*HH; }
    else       { dst = g_X[cur^1]; drow = (nbase + t)*HH; }

    int el = g_excl[0][b*TT+t], ei = g_excl[1][b*TT+t];
    int srcs[9];
    srcs[0]=t;
    srcs[1]=(t>0)? t-1 : t;
    srcs[2]=(t<TT-1)? t+1 : t;
    srcs[3]=0 + (0>=el);           // heavy-local indices 0..7
    srcs[4]=1 + (1>=el);
    srcs[5]=2 + (2>=el);
    srcs[6]=LL + 0 + (0>=ei);
    srcs[7]=LL + 1 + (1>=ei);
    srcs[8]=LL + 2 + (2>=ei);
    bool valid1 = (t>0), valid2 = (t<TT-1);

    float4 adv = ((const float4*)g_ad)[nbase + t];
    float adh[4] = {adv.x, adv.y, adv.z, adv.w};
    float w[9][4];
    float mx[4] = {-1e30f,-1e30f,-1e30f,-1e30f};
    #pragma unroll
    for (int e=0;e<9;e++){
        float4 av;
        if (e < 3) av = ((const float4*)g_as)[nbase + srcs[e]];
        else       av = *(const float4*)&s_as[srcs[e]*4];
        float a[4] = {av.x,av.y,av.z,av.w};
        bool v = (e==1)? valid1 : ((e==2)? valid2 : true);
        #pragma unroll
        for (int h=0;h<4;h++){
            float ev = lrelu(a[h] + adh[h]);
            ev = v ? ev : -1e30f;
            w[e][h]=ev;
            mx[h]=fmaxf(mx[h],ev);
        }
    }
    float den[4]={0,0,0,0};
    #pragma unroll
    for (int e=0;e<9;e++)
        #pragma unroll
        for (int h=0;h<4;h++){ float ex=expf(w[e][h]-mx[h]); w[e][h]=ex; den[h]+=ex; }
    #pragma unroll
    for (int h=0;h<4;h++) den[h] = 1.f/(den[h]+1e-16f);
    #pragma unroll
    for (int e=0;e<9;e++)
        #pragma unroll
        for (int h=0;h<4;h++) w[e][h]*=den[h];

    float acc[24];
    #pragma unroll
    for (int i=0;i<24;i++) acc[i]=0.f;
    const float* Hb = g_H + nbase*HH;
    #pragma unroll
    for (int e=0;e<3;e++){
        const float* hr = Hb + (size_t)srcs[e]*HH + lane;
        #pragma unroll
        for (int i=0;i<24;i++) acc[i] += w[e][i/6]*hr[32*i];
    }
    #pragma unroll
    for (int e=3;e<9;e++){
        const float* hr = s_h + srcs[e]*HH + lane;
        #pragma unroll
        for (int i=0;i<24;i++) acc[i] += w[e][i/6]*hr[32*i];
    }
    const float* xr = Xcur + (nbase + t)*HH + lane;
    float s=0.f;
    #pragma unroll
    for (int i=0;i<24;i++){
        int c = lane + 32*i;
        float v = fmaxf(acc[i] + bias[c], 0.f) + xr[32*i];
        acc[i]=v; s+=v;
    }
    s = warpSum(s);
    float mean = s*(1.f/HH);
    float q=0.f;
    #pragma unroll
    for (int i=0;i<24;i++){ float dd=acc[i]-mean; q+=dd*dd; }
    q = warpSum(q);
    float rstd = rsqrtf(q*(1.f/HH)+1e-5f);
    if (isLast){
        #pragma unroll
        for (int i=0;i<24;i++){
            int c = lane+32*i;
            dst[drow + c] = (acc[i]-mean)*rstd*gamma[c] + beta[c];
        }
    } else {
        #pragma unroll
        for (int i=0;i<24;i++){
            int c = lane+32*i;
            float o = (acc[i]-mean)*rstd*gamma[c] + beta[c];
            dst[drow + c] = o;
            __nv_bfloat16 h = __float2bfloat16(o);
            g_Ahi[drow + c] = h;
            g_Alo[drow + c] = bflo(o, h);
        }
    }
}

// ---------------- heavy dsts: ONE block per batch handles all 8 dsts ----------
// smem weights layout: s_wt[t*40 + h*8 + d]  (pad 40 -> 16B-aligned float4 per (t,h))
#define HV_WSZ (520*40)
__global__ void __launch_bounds__(768) k_heavy2(int cur, const float* __restrict__ bias,
        const float* __restrict__ gamma, const float* __restrict__ beta)
{
    extern __shared__ float s_wt[];          // HV_WSZ floats
    __shared__ float s_mx[4];
    __shared__ float s_redm[17*4];
    __shared__ float s_redd[17*4];
    __shared__ float s_dinv[32];             // [d*4+h]
    __shared__ float s_red[24], s_red2[24];
    __shared__ float s_stats[2];

    int b = blockIdx.x;
    int tid = threadIdx.x, wid = tid>>5, lane = tid&31;
    size_t nbase = (size_t)b*NN;

    // ---- Phase A: softmax weights for all 8 dsts ----
    for (int d=0; d<8; d++){
        int dl = d&3;
        const int* excl = g_excl[d>>2] + b*TT;
        float4 adv = ((const float4*)g_ad)[nbase + TT + d];
        float e0=-1e30f, e1=-1e30f, e2=-1e30f, e3=-1e30f;
        if (tid < NN){
            bool v = (tid >= TT) || (excl[tid] != dl);
            float4 av = ((const float4*)g_as)[nbase + tid];
            if (v){
                e0 = lrelu(av.x + adv.x);
                e1 = lrelu(av.y + adv.y);
                e2 = lrelu(av.z + adv.z);
                e3 = lrelu(av.w + adv.w);
            }
        }
        if (wid < 17){
            float m0=warpMax(e0), m1=warpMax(e1), m2=warpMax(e2), m3=warpMax(e3);
            if (lane==0){ s_redm[wid*4+0]=m0; s_redm[wid*4+1]=m1; s_redm[wid*4+2]=m2; s_redm[wid*4+3]=m3; }
        }
        __syncthreads();
        if (tid < 4){
            float m=-1e30f;
            #pragma unroll
            for (int wg=0; wg<17; wg++) m = fmaxf(m, s_redm[wg*4+tid]);
            s_mx[tid] = m;
        }
        __syncthreads();
        float x0=0.f,x1=0.f,x2=0.f,x3=0.f;
        if (tid < NN){
            x0 = expf(e0 - s_mx[0]);
            x1 = expf(e1 - s_mx[1]);
            x2 = expf(e2 - s_mx[2]);
            x3 = expf(e3 - s_mx[3]);
            s_wt[tid*40 + 0*8 + d] = x0;
            s_wt[tid*40 + 1*8 + d] = x1;
            s_wt[tid*40 + 2*8 + d] = x2;
            s_wt[tid*40 + 3*8 + d] = x3;
        }
        if (wid < 17){
            float d0=warpSum(x0), d1=warpSum(x1), d2=warpSum(x2), d3=warpSum(x3);
            if (lane==0){ s_redd[wid*4+0]=d0; s_redd[wid*4+1]=d1; s_redd[wid*4+2]=d2; s_redd[wid*4+3]=d3; }
        }
        __syncthreads();
        if (tid < 4){
            float sm=0.f;
            #pragma unroll
            for (int wg=0; wg<17; wg++) sm += s_redd[wg*4+tid];
            s_dinv[d*4+tid] = 1.f/(sm + 1e-16f);
        }
        __syncthreads();
    }

    // ---- Phase B: aggregation. thread = one column, 8 dst accumulators ----
    int c = tid;                 // 0..767
    int h = c / DOUT;            // warp-uniform (192 % 32 == 0)
    const float* Hb = g_H + nbase*HH;
    float a[8];
    #pragma unroll
    for (int d=0;d<8;d++) a[d]=0.f;
    for (int t=0; t<NN; t++){
        float hr = Hb[(size_t)t*HH + c];
        float4 w0 = *(const float4*)&s_wt[t*40 + h*8];
        float4 w1 = *(const float4*)&s_wt[t*40 + h*8 + 4];
        a[0] += w0.x*hr; a[1] += w0.y*hr; a[2] += w0.z*hr; a[3] += w0.w*hr;
        a[4] += w1.x*hr; a[5] += w1.y*hr; a[6] += w1.z*hr; a[7] += w1.w*hr;
    }
    float y[8];
    float bi = bias[c];
    #pragma unroll
    for (int d=0;d<8;d++){
        float agg = a[d]*s_dinv[d*4+h];
        y[d] = fmaxf(agg + bi, 0.f) + g_X[cur][(nbase + TT + d)*HH + c];
    }

    // ---- Phase C: LN + write per dst ----
    float gm = gamma[c], bt = beta[c];
    for (int d=0;d<8;d++){
        float ps = warpSum(y[d]);
        float pq = warpSum(y[d]*y[d]);
        if (lane==0){ s_red[wid]=ps; s_red2[wid]=pq; }
        __syncthreads();
        if (tid==0){
            float S=0.f,Q=0.f;
            #pragma unroll
            for (int wg=0;wg<24;wg++){ S+=s_red[wg]; Q+=s_red2[wg]; }
            float mean = S*(1.f/HH);
            float var  = Q*(1.f/HH) - mean*mean;
            s_stats[0]=mean;
            s_stats[1]=rsqrtf(fmaxf(var,0.f)+1e-5f);
        }
        __syncthreads();
        float mean=s_stats[0], rstd=s_stats[1];
        size_t row = (nbase + TT + d)*HH;
        float o = (y[d]-mean)*rstd*gm + bt;
        g_X[cur^1][row + c] = o;
        __nv_bfloat16 hh = __float2bfloat16(o);
        g_Ahi[row + c] = hh;
        g_Alo[row + c] = bflo(o, hh);
    }
}

// ---------------- launch ----------------
extern "C" void kernel_launch(void* const* d_in, const int* in_sizes, int n_in,
                              void* d_out, int out_size)
{
    const float* text = (const float*)d_in[0];
    const float* lab  = (const float*)d_in[1];
    const float* img  = (const float*)d_in[2];
    const float* Ws   = (const float*)d_in[3];
    const float* aws  = (const float*)d_in[4];
    const float* awd  = (const float*)d_in[5];
    const float* bias = (const float*)d_in[6];
    const float* gam  = (const float*)d_in[7];
    const float* bet  = (const float*)d_in[8];
    float* outp = (float*)d_out;

    cudaFuncSetAttribute(k_gemm_mma, cudaFuncAttributeMaxDynamicSharedMemorySize, GSMEM);
    cudaFuncSetAttribute(k_heavy2, cudaFuncAttributeMaxDynamicSharedMemorySize, HV_WSZ*4);

    k_wconv<<<(3*HH*HH + 255)/256, 256>>>(Ws);
    {
        size_t total = (size_t)BATCH*NN*H4;
        int blocks = (int)((total + 255)/256);
        k_concat<<<blocks,256>>>((const float4*)text,(const float4*)lab,(const float4*)img);
    }
    k_excl<<<BATCH,256>>>(text, lab, img);

    int cur = 0;
    for (int l=0;l<3;l++){
        k_gemm_mma<<<dim3((BATCH*NN)/128, HH/256), 256, GSMEM>>>(l);
        k_alpha<<<(BATCH*NN)/8,256>>>(aws + l*HH, awd + l*HH);
        int last = (l==2);
        k_text<<<(BATCH*TT)/8,256>>>(cur, bias+l*HH, gam+l*HH, bet+l*HH, outp, last);
        if (!last) k_heavy2<<<BATCH, 768, HV_WSZ*4>>>(cur, bias+l*HH, gam+l*HH, bet+l*HH);
        cur ^= 1;
    }
}

// round 8
// speedup vs baseline: 1.7691x; 1.1051x over previous
#include <cuda_runtime.h>
#include <cuda_bf16.h>
#include <math.h>
#include <stdint.h>

#define BATCH 64
#define TT 512
#define LL 4
#define II 4
#define NN 520          // TT+LL+II
#define HH 768
#define NH 4
#define DOUT 192
#define H4 (HH/4)
#define KCH 36          // 36 K-chunks of 64 (hi,hi,lo x 12)

// ---------------- scratch (device globals; no allocations allowed) ----------------
__device__ float g_X[2][(size_t)BATCH*NN*HH];   // ping-pong node features (fp32 residual path)
__device__ float g_H[(size_t)BATCH*NN*HH];      // h = X @ W^T
__device__ float g_as[BATCH*NN*NH];             // (h*a_s).sum(-1)
__device__ float g_ad[BATCH*NN*NH];             // (h*a_d).sum(-1)
__device__ int   g_excl[2][BATCH*TT];           // [0]=excluded label idx, [1]=excluded image idx
__device__ __nv_bfloat16 g_Ahi[(size_t)BATCH*NN*HH];  // bf16 hi(X)
__device__ __nv_bfloat16 g_Alo[(size_t)BATCH*NN*HH];  // bf16 lo(X)
__device__ __nv_bfloat16 g_Wh[(size_t)3*HH*HH];       // bf16 hi(W)
__device__ __nv_bfloat16 g_Wl[(size_t)3*HH*HH];       // bf16 lo(W)

__device__ __forceinline__ float warpSum(float v){
    #pragma unroll
    for (int o=16;o;o>>=1) v += __shfl_xor_sync(0xffffffffu, v, o);
    return v;
}
__device__ __forceinline__ float warpMax(float v){
    #pragma unroll
    for (int o=16;o;o>>=1) v = fmaxf(v, __shfl_xor_sync(0xffffffffu, v, o));
    return v;
}
__device__ __forceinline__ float lrelu(float x){ return x > 0.f ? x : 0.2f*x; }

__device__ __forceinline__ uint32_t smem_u32(const void* p){
    uint32_t a;
    asm("{ .reg .u64 t; cvta.to.shared.u64 t, %1; cvt.u32.u64 %0, t; }" : "=r"(a) : "l"(p));
    return a;
}
__device__ __forceinline__ __nv_bfloat16 bflo(float x, __nv_bfloat16 h){
    return __float2bfloat16(x - __bfloat162float(h));
}

// ---------------- W -> bf16 hi/lo ----------------
__global__ void k_wconv(const float* __restrict__ Ws){
    size_t i = (size_t)blockIdx.x*256 + threadIdx.x;
    if (i >= (size_t)3*HH*HH) return;
    float w = Ws[i];
    __nv_bfloat16 h = __float2bfloat16(w);
    g_Wh[i] = h;
    g_Wl[i] = bflo(w, h);
}

// ---------------- concat [text;label;image] -> X0 (+ bf16 hi/lo) ----------------
__global__ void k_concat(const float4* __restrict__ text, const float4* __restrict__ lab,
                         const float4* __restrict__ img)
{
    size_t idx = (size_t)blockIdx.x*blockDim.x + threadIdx.x;
    const size_t total = (size_t)BATCH*NN*H4;
    if (idx >= total) return;
    int b = (int)(idx / (NN*H4));
    int r = (int)(idx % (NN*H4));
    int n = r / H4;
    int k = r % H4;
    float4 v;
    if (n < TT)          v = text[(size_t)b*TT*H4 + (size_t)n*H4 + k];
    else if (n < TT+LL)  v = lab [(size_t)b*LL*H4 + (size_t)(n-TT)*H4 + k];
    else                 v = img [(size_t)b*II*H4 + (size_t)(n-TT-LL)*H4 + k];
    ((float4*)g_X[0])[idx] = v;
    __nv_bfloat16 hx=__float2bfloat16(v.x), hy=__float2bfloat16(v.y);
    __nv_bfloat16 hz=__float2bfloat16(v.z), hw=__float2bfloat16(v.w);
    ((__nv_bfloat162*)g_Ahi)[2*idx]   = __halves2bfloat162(hx,hy);
    ((__nv_bfloat162*)g_Ahi)[2*idx+1] = __halves2bfloat162(hz,hw);
    ((__nv_bfloat162*)g_Alo)[2*idx]   = __halves2bfloat162(bflo(v.x,hx), bflo(v.y,hy));
    ((__nv_bfloat162*)g_Alo)[2*idx+1] = __halves2bfloat162(bflo(v.z,hz), bflo(v.w,hw));
}

// ---------------- dynamic edges ----------------
__global__ void k_excl(const float* __restrict__ text, const float* __restrict__ lab,
                       const float* __restrict__ img)
{
    __shared__ float sh[8*HH];
    __shared__ float sinv[8];
    int b = blockIdx.x;
    int tid = threadIdx.x;
    for (int i=tid;i<LL*HH;i+=blockDim.x) sh[i]       = lab[(size_t)b*LL*HH + i];
    for (int i=tid;i<II*HH;i+=blockDim.x) sh[LL*HH+i] = img[(size_t)b*II*HH + i];
    __syncthreads();
    int wid = tid>>5, lane = tid&31;
    if (wid < 8){
        float s=0.f;
        for (int k=lane;k<HH;k+=32){ float v=sh[wid*HH+k]; s+=v*v; }
        s = warpSum(s);
        if (lane==0) sinv[wid] = 1.f / fmaxf(sqrtf(s), 1e-8f);
    }
    __syncthreads();
    for (int t=wid;t<TT;t+=8){
        const float* xr = text + (size_t)b*TT*HH + (size_t)t*HH;
        float d0=0,d1=0,d2=0,d3=0,d4=0,d5=0,d6=0,d7=0;
        for (int k=lane;k<HH;k+=32){
            float x = xr[k];
            d0+=x*sh[0*HH+k]; d1+=x*sh[1*HH+k]; d2+=x*sh[2*HH+k]; d3+=x*sh[3*HH+k];
            d4+=x*sh[4*HH+k]; d5+=x*sh[5*HH+k]; d6+=x*sh[6*HH+k]; d7+=x*sh[7*HH+k];
        }
        d0=warpSum(d0); d1=warpSum(d1); d2=warpSum(d2); d3=warpSum(d3);
        d4=warpSum(d4); d5=warpSum(d5); d6=warpSum(d6); d7=warpSum(d7);
        if (lane==0){
            float c0=d0*sinv[0], c1=d1*sinv[1], c2=d2*sinv[2], c3=d3*sinv[3];
            int el=0; float bm=c0;
            if (c1<bm){bm=c1;el=1;} if (c2<bm){bm=c2;el=2;} if (c3<bm){bm=c3;el=3;}
            g_excl[0][b*TT+t]=el;
            float e0=d4*sinv[4], e1=d5*sinv[5], e2=d6*sinv[6], e3=d7*sinv[7];
            int ei=0; bm=e0;
            if (e1<bm){bm=e1;ei=1;} if (e2<bm){bm=e2;ei=2;} if (e3<bm){bm=e3;ei=3;}
            g_excl[1][b*TT+t]=ei;
        }
    }
}

// ---------------- mma.sync bf16-split GEMM: g_H = X @ W^T ----------------
// CTA tile 128x128, BK=64, 8 warps (2x4, 64x32 warp tiles), 2-stage cp.async,
// SINGLE __syncthreads per k-chunk (loads of c+1 overlap compute of c).
#define BK 64
#define LDSM 72
#define STG_A (128*LDSM*2)            // 18432
#define STG   (2*STG_A)               // A+B per stage = 36864
#define GSMEM (2*STG)                 // 73728 -> 2 CTAs/SM

__device__ __forceinline__ void cp16(uint32_t dst, const void* src){
    asm volatile("cp.async.cg.shared.global [%0], [%1], 16;" :: "r"(dst), "l"(src));
}

__global__ void __launch_bounds__(256) k_gemm_mma(int layer)
{
    extern __shared__ __align__(16) char dsm[];
    uint32_t smem = smem_u32(dsm);
    int tid = threadIdx.x, lane = tid&31, wid = tid>>5;
    int warp_m = (wid&1)*64;
    int warp_n = (wid>>1)*32;

    const __nv_bfloat16* Wb  = g_Wh + (size_t)layer*HH*HH;
    const __nv_bfloat16* Wlb = g_Wl + (size_t)layer*HH*HH;
    size_t arow0 = (size_t)blockIdx.x*128;
    size_t brow0 = (size_t)blockIdx.y*128;

    float acc[4][4][4];
    #pragma unroll
    for (int mi=0;mi<4;mi++)
        #pragma unroll
        for (int nj=0;nj<4;nj++)
            #pragma unroll
            for (int r=0;r<4;r++) acc[mi][nj][r]=0.f;

    auto issue = [&](int c, int s){
        const __nv_bfloat16* Asrc = (c<24)? g_Ahi : g_Alo;
        const __nv_bfloat16* Bsrc = (c<12)? Wb : ((c<24)? Wlb : Wb);
        int col = (c%12)*BK;
        uint32_t sa  = smem + s*STG;
        uint32_t sbm = smem + s*STG + STG_A;
        #pragma unroll
        for (int i=0;i<4;i++){
            int idx = tid + i*256;
            int r = idx>>3, q = idx&7;
            cp16(sa + (uint32_t)(r*LDSM + q*8)*2,
                 Asrc + (arow0 + r)*HH + col + q*8);
        }
        #pragma unroll
        for (int i=0;i<4;i++){
            int idx = tid + i*256;
            int r = idx>>3, q = idx&7;
            cp16(sbm + (uint32_t)(r*LDSM + q*8)*2,
                 Bsrc + (brow0 + r)*HH + col + q*8);
        }
        asm volatile("cp.async.commit_group;" ::: "memory");
    };

    issue(0,0);

    for (int c=0;c<KCH;c++){
        int s = c&1;
        asm volatile("cp.async.wait_group 0;" ::: "memory");
        __syncthreads();                       // all of stage s ready; all done with s^1
        if (c+1 < KCH) issue(c+1, s^1);        // overlap next loads with compute below

        uint32_t saA = smem + s*STG;
        uint32_t saB = smem + s*STG + STG_A;
        #pragma unroll
        for (int ks=0;ks<4;ks++){
            int kb = ks*16;
            uint32_t aF[4][4];
            uint32_t bF[4][2];
            #pragma unroll
            for (int mi=0;mi<4;mi++){
                int row = warp_m + mi*16 + (lane&15);
                int col = kb + ((lane>>4)<<3);
                uint32_t ad = saA + (uint32_t)(row*LDSM + col)*2;
                asm volatile("ldmatrix.sync.aligned.m8n8.x4.shared.b16 {%0,%1,%2,%3}, [%4];"
                    : "=r"(aF[mi][0]), "=r"(aF[mi][1]), "=r"(aF[mi][2]), "=r"(aF[mi][3])
                    : "r"(ad));
            }
            #pragma unroll
            for (int ng=0;ng<2;ng++){
                int n = warp_n + ng*16 + (lane&7) + ((lane>>4)<<3);
                int k = kb + (((lane>>3)&1)<<3);
                uint32_t ad = saB + (uint32_t)(n*LDSM + k)*2;
                uint32_t r0,r1,r2,r3;
                asm volatile("ldmatrix.sync.aligned.m8n8.x4.shared.b16 {%0,%1,%2,%3}, [%4];"
                    : "=r"(r0), "=r"(r1), "=r"(r2), "=r"(r3) : "r"(ad));
                bF[ng*2+0][0]=r0; bF[ng*2+0][1]=r1;
                bF[ng*2+1][0]=r2; bF[ng*2+1][1]=r3;
            }
            #pragma unroll
            for (int mi=0;mi<4;mi++)
                #pragma unroll
                for (int nj=0;nj<4;nj++){
                    asm volatile(
                        "mma.sync.aligned.m16n8k16.row.col.f32.bf16.bf16.f32 "
                        "{%0,%1,%2,%3}, {%4,%5,%6,%7}, {%8,%9}, {%0,%1,%2,%3};"
                        : "+f"(acc[mi][nj][0]), "+f"(acc[mi][nj][1]),
                          "+f"(acc[mi][nj][2]), "+f"(acc[mi][nj][3])
                        : "r"(aF[mi][0]), "r"(aF[mi][1]), "r"(aF[mi][2]), "r"(aF[mi][3]),
                          "r"(bF[nj][0]), "r"(bF[nj][1]));
                }
        }
        // no trailing sync: next iteration's barrier protects stage reuse
    }

    // epilogue
    int g = lane>>2, t2 = (lane&3)*2;
    #pragma unroll
    for (int mi=0;mi<4;mi++){
        size_t row = arow0 + warp_m + mi*16 + g;
        float* cr0 = g_H + row*HH + brow0 + warp_n;
        float* cr1 = g_H + (row+8)*HH + brow0 + warp_n;
        #pragma unroll
        for (int nj=0;nj<4;nj++){
            int col = nj*8 + t2;
            *(float2*)(cr0 + col) = make_float2(acc[mi][nj][0], acc[mi][nj][1]);
            *(float2*)(cr1 + col) = make_float2(acc[mi][nj][2], acc[mi][nj][3]);
        }
    }
}

// ---------------- per-node attention logits alpha_s/alpha_d ----------------
__global__ void __launch_bounds__(256) k_alpha(const float* __restrict__ aw_s,
                                               const float* __restrict__ aw_d)
{
    __shared__ float s_s[HH], s_d[HH];
    for (int i=threadIdx.x;i<HH;i+=256){ s_s[i]=aw_s[i]; s_d[i]=aw_d[i]; }
    __syncthreads();
    int wid = threadIdx.x>>5, lane = threadIdx.x&31;
    int row = blockIdx.x*8 + wid;
    if (row >= BATCH*NN) return;
    const float* h = g_H + (size_t)row*HH;
    #pragma unroll
    for (int hh=0; hh<NH; hh++){
        float s=0.f, d=0.f;
        #pragma unroll
        for (int k=lane;k<DOUT;k+=32){
            float hv = h[hh*DOUT+k];
            s += hv*s_s[hh*DOUT+k];
            d += hv*s_d[hh*DOUT+k];
        }
        s = warpSum(s); d = warpSum(d);
        if (lane==0){ g_as[row*NH+hh]=s; g_ad[row*NH+hh]=d; }
    }
}

// ---------------- text dsts: one warp per (b,t); heavy rows staged in smem ----------
__global__ void __launch_bounds__(256) k_text(int cur, const float* __restrict__ bias,
        const float* __restrict__ gamma, const float* __restrict__ beta,
        float* __restrict__ outp, int isLast)
{
    __shared__ float s_h[8*HH];    // 8 heavy H rows (24KB)
    __shared__ float s_as[32];     // heavy as values
    int tid = threadIdx.x;
    int lane = tid & 31;
    int b = blockIdx.x >> 6;       // 64 blocks per batch
    size_t nbase = (size_t)b*NN;

    {
        const float4* hs = (const float4*)(g_H + (nbase + TT)*HH);
        #pragma unroll
        for (int i=0;i<6;i++) ((float4*)s_h)[tid + i*256] = hs[tid + i*256];
        if (tid < 32) s_as[tid] = g_as[(nbase + TT)*NH + tid];
    }
    __syncthreads();

    int gw = blockIdx.x*8 + (tid>>5);
    int t = gw % TT;
    const float* Xcur = g_X[cur];
    float* dst; size_t drow;
    if (isLast){ dst = outp;       drow = ((size_t)b*TT + t)*HH; }
    else       { dst = g_X[cur^1]; drow = (nbase + t)*HH; }

    int el = g_excl[0][b*TT+t], ei = g_excl[1][b*TT+t];
    int srcs[9];
    srcs[0]=t;
    srcs[1]=(t>0)? t-1 : t;
    srcs[2]=(t<TT-1)? t+1 : t;
    srcs[3]=0 + (0>=el);
    srcs[4]=1 + (1>=el);
    srcs[5]=2 + (2>=el);
    srcs[6]=LL + 0 + (0>=ei);
    srcs[7]=LL + 1 + (1>=ei);
    srcs[8]=LL + 2 + (2>=ei);
    bool valid1 = (t>0), valid2 = (t<TT-1);

    float4 adv = ((const float4*)g_ad)[nbase + t];
    float adh[4] = {adv.x, adv.y, adv.z, adv.w};
    float w[9][4];
    float mx[4] = {-1e30f,-1e30f,-1e30f,-1e30f};
    #pragma unroll
    for (int e=0;e<9;e++){
        float4 av;
        if (e < 3) av = ((const float4*)g_as)[nbase + srcs[e]];
        else       av = *(const float4*)&s_as[srcs[e]*4];
        float a[4] = {av.x,av.y,av.z,av.w};
        bool v = (e==1)? valid1 : ((e==2)? valid2 : true);
        #pragma unroll
        for (int h=0;h<4;h++){
            float ev = lrelu(a[h] + adh[h]);
            ev = v ? ev : -1e30f;
            w[e][h]=ev;
            mx[h]=fmaxf(mx[h],ev);
        }
    }
    float den[4]={0,0,0,0};
    #pragma unroll
    for (int e=0;e<9;e++)
        #pragma unroll
        for (int h=0;h<4;h++){ float ex=expf(w[e][h]-mx[h]); w[e][h]=ex; den[h]+=ex; }
    #pragma unroll
    for (int h=0;h<4;h++) den[h] = 1.f/(den[h]+1e-16f);
    #pragma unroll
    for (int e=0;e<9;e++)
        #pragma unroll
        for (int h=0;h<4;h++) w[e][h]*=den[h];

    float acc[24];
    #pragma unroll
    for (int i=0;i<24;i++) acc[i]=0.f;
    const float* Hb = g_H + nbase*HH;
    #pragma unroll
    for (int e=0;e<3;e++){
        const float* hr = Hb + (size_t)srcs[e]*HH + lane;
        #pragma unroll
        for (int i=0;i<24;i++) acc[i] += w[e][i/6]*hr[32*i];
    }
    #pragma unroll
    for (int e=3;e<9;e++){
        const float* hr = s_h + srcs[e]*HH + lane;
        #pragma unroll
        for (int i=0;i<24;i++) acc[i] += w[e][i/6]*hr[32*i];
    }
    const float* xr = Xcur + (nbase + t)*HH + lane;
    float s=0.f;
    #pragma unroll
    for (int i=0;i<24;i++){
        int c = lane + 32*i;
        float v = fmaxf(acc[i] + bias[c], 0.f) + xr[32*i];
        acc[i]=v; s+=v;
    }
    s = warpSum(s);
    float mean = s*(1.f/HH);
    float q=0.f;
    #pragma unroll
    for (int i=0;i<24;i++){ float dd=acc[i]-mean; q+=dd*dd; }
    q = warpSum(q);
    float rstd = rsqrtf(q*(1.f/HH)+1e-5f);
    if (isLast){
        #pragma unroll
        for (int i=0;i<24;i++){
            int c = lane+32*i;
            dst[drow + c] = (acc[i]-mean)*rstd*gamma[c] + beta[c];
        }
    } else {
        #pragma unroll
        for (int i=0;i<24;i++){
            int c = lane+32*i;
            float o = (acc[i]-mean)*rstd*gamma[c] + beta[c];
            dst[drow + c] = o;
            __nv_bfloat16 h = __float2bfloat16(o);
            g_Ahi[drow + c] = h;
            g_Alo[drow + c] = bflo(o, h);
        }
    }
}

// ---------------- heavy dsts: ONE block per batch handles all 8 dsts ----------
#define HV_WSZ (520*40)
__global__ void __launch_bounds__(768) k_heavy2(int cur, const float* __restrict__ bias,
        const float* __restrict__ gamma, const float* __restrict__ beta)
{
    extern __shared__ float s_wt[];          // HV_WSZ floats
    __shared__ float s_mx[4];
    __shared__ float s_redm[17*4];
    __shared__ float s_redd[17*4];
    __shared__ float s_dinv[32];             // [d*4+h]
    __shared__ float s_red[24], s_red2[24];
    __shared__ float s_stats[2];

    int b = blockIdx.x;
    int tid = threadIdx.x, wid = tid>>5, lane = tid&31;
    size_t nbase = (size_t)b*NN;

    for (int d=0; d<8; d++){
        int dl = d&3;
        const int* excl = g_excl[d>>2] + b*TT;
        float4 adv = ((const float4*)g_ad)[nbase + TT + d];
        float e0=-1e30f, e1=-1e30f, e2=-1e30f, e3=-1e30f;
        if (tid < NN){
            bool v = (tid >= TT) || (excl[tid] != dl);
            float4 av = ((const float4*)g_as)[nbase + tid];
            if (v){
                e0 = lrelu(av.x + adv.x);
                e1 = lrelu(av.y + adv.y);
                e2 = lrelu(av.z + adv.z);
                e3 = lrelu(av.w + adv.w);
            }
        }
        if (wid < 17){
            float m0=warpMax(e0), m1=warpMax(e1), m2=warpMax(e2), m3=warpMax(e3);
            if (lane==0){ s_redm[wid*4+0]=m0; s_redm[wid*4+1]=m1; s_redm[wid*4+2]=m2; s_redm[wid*4+3]=m3; }
        }
        __syncthreads();
        if (tid < 4){
            float m=-1e30f;
            #pragma unroll
            for (int wg=0; wg<17; wg++) m = fmaxf(m, s_redm[wg*4+tid]);
            s_mx[tid] = m;
        }
        __syncthreads();
        float x0=0.f,x1=0.f,x2=0.f,x3=0.f;
        if (tid < NN){
            x0 = expf(e0 - s_mx[0]);
            x1 = expf(e1 - s_mx[1]);
            x2 = expf(e2 - s_mx[2]);
            x3 = expf(e3 - s_mx[3]);
            s_wt[tid*40 + 0*8 + d] = x0;
            s_wt[tid*40 + 1*8 + d] = x1;
            s_wt[tid*40 + 2*8 + d] = x2;
            s_wt[tid*40 + 3*8 + d] = x3;
        }
        if (wid < 17){
            float d0=warpSum(x0), d1=warpSum(x1), d2=warpSum(x2), d3=warpSum(x3);
            if (lane==0){ s_redd[wid*4+0]=d0; s_redd[wid*4+1]=d1; s_redd[wid*4+2]=d2; s_redd[wid*4+3]=d3; }
        }
        __syncthreads();
        if (tid < 4){
            float sm=0.f;
            #pragma unroll
            for (int wg=0; wg<17; wg++) sm += s_redd[wg*4+tid];
            s_dinv[d*4+tid] = 1.f/(sm + 1e-16f);
        }
        __syncthreads();
    }

    int c = tid;
    int h = c / DOUT;
    const float* Hb = g_H + nbase*HH;
    float a[8];
    #pragma unroll
    for (int d=0;d<8;d++) a[d]=0.f;
    for (int t=0; t<NN; t++){
        float hr = Hb[(size_t)t*HH + c];
        float4 w0 = *(const float4*)&s_wt[t*40 + h*8];
        float4 w1 = *(const float4*)&s_wt[t*40 + h*8 + 4];
        a[0] += w0.x*hr; a[1] += w0.y*hr; a[2] += w0.z*hr; a[3] += w0.w*hr;
        a[4] += w1.x*hr; a[5] += w1.y*hr; a[6] += w1.z*hr; a[7] += w1.w*hr;
    }
    float y[8];
    float bi = bias[c];
    #pragma unroll
    for (int d=0;d<8;d++){
        float agg = a[d]*s_dinv[d*4+h];
        y[d] = fmaxf(agg + bi, 0.f) + g_X[cur][(nbase + TT + d)*HH + c];
    }

    float gm = gamma[c], bt = beta[c];
    for (int d=0;d<8;d++){
        float ps = warpSum(y[d]);
        float pq = warpSum(y[d]*y[d]);
        if (lane==0){ s_red[wid]=ps; s_red2[wid]=pq; }
        __syncthreads();
        if (tid==0){
            float S=0.f,Q=0.f;
            #pragma unroll
            for (int wg=0;wg<24;wg++){ S+=s_red[wg]; Q+=s_red2[wg]; }
            float mean = S*(1.f/HH);
            float var  = Q*(1.f/HH) - mean*mean;
            s_stats[0]=mean;
            s_stats[1]=rsqrtf(fmaxf(var,0.f)+1e-5f);
        }
        __syncthreads();
        float mean=s_stats[0], rstd=s_stats[1];
        size_t row = (nbase + TT + d)*HH;
        float o = (y[d]-mean)*rstd*gm + bt;
        g_X[cur^1][row + c] = o;
        __nv_bfloat16 hh = __float2bfloat16(o);
        g_Ahi[row + c] = hh;
        g_Alo[row + c] = bflo(o, hh);
    }
}

// ---------------- launch ----------------
extern "C" void kernel_launch(void* const* d_in, const int* in_sizes, int n_in,
                              void* d_out, int out_size)
{
    const float* text = (const float*)d_in[0];
    const float* lab  = (const float*)d_in[1];
    const float* img  = (const float*)d_in[2];
    const float* Ws   = (const float*)d_in[3];
    const float* aws  = (const float*)d_in[4];
    const float* awd  = (const float*)d_in[5];
    const float* bias = (const float*)d_in[6];
    const float* gam  = (const float*)d_in[7];
    const float* bet  = (const float*)d_in[8];
    float* outp = (float*)d_out;

    cudaFuncSetAttribute(k_gemm_mma, cudaFuncAttributeMaxDynamicSharedMemorySize, GSMEM);
    cudaFuncSetAttribute(k_heavy2, cudaFuncAttributeMaxDynamicSharedMemorySize, HV_WSZ*4);

    k_wconv<<<(3*HH*HH + 255)/256, 256>>>(Ws);
    {
        size_t total = (size_t)BATCH*NN*H4;
        int blocks = (int)((total + 255)/256);
        k_concat<<<blocks,256>>>((const float4*)text,(const float4*)lab,(const float4*)img);
    }
    k_excl<<<BATCH,256>>>(text, lab, img);

    int cur = 0;
    for (int l=0;l<3;l++){
        k_gemm_mma<<<dim3((BATCH*NN)/128, HH/128), 256, GSMEM>>>(l);
        k_alpha<<<(BATCH*NN)/8,256>>>(aws + l*HH, awd + l*HH);
        int last = (l==2);
        k_text<<<(BATCH*TT)/8,256>>>(cur, bias+l*HH, gam+l*HH, bet+l*HH, outp, last);
        if (!last) k_heavy2<<<BATCH, 768, HV_WSZ*4>>>(cur, bias+l*HH, gam+l*HH, bet+l*HH);
        cur ^= 1;
    }
}

// round 9
// speedup vs baseline: 1.8121x; 1.0243x over previous
#include <cuda_runtime.h>
#include <cuda_bf16.h>
#include <math.h>
#include <stdint.h>

#define BATCH 64
#define TT 512
#define LL 4
#define II 4
#define NN 520          // TT+LL+II
#define HH 768
#define NH 4
#define DOUT 192
#define H4 (HH/4)
#define KCH 36          // 36 K-chunks of 64 (hi,hi,lo x 12)

// ---------------- scratch (device globals; no allocations allowed) ----------------
__device__ float g_X[2][(size_t)BATCH*NN*HH];   // ping-pong node features (fp32 residual path)
__device__ float g_H[(size_t)BATCH*NN*HH];      // h = X @ W^T
__device__ float g_as[BATCH*NN*NH];             // (h*a_s).sum(-1)
__device__ float g_ad[BATCH*NN*NH];             // (h*a_d).sum(-1)
__device__ int   g_excl[2][BATCH*TT];           // [0]=excluded label idx, [1]=excluded image idx
__device__ __nv_bfloat16 g_Ahi[(size_t)BATCH*NN*HH];  // bf16 hi(X)
__device__ __nv_bfloat16 g_Alo[(size_t)BATCH*NN*HH];  // bf16 lo(X)
__device__ __nv_bfloat16 g_Wh[(size_t)3*HH*HH];       // bf16 hi(W)
__device__ __nv_bfloat16 g_Wl[(size_t)3*HH*HH];       // bf16 lo(W)

__device__ __forceinline__ float warpSum(float v){
    #pragma unroll
    for (int o=16;o;o>>=1) v += __shfl_xor_sync(0xffffffffu, v, o);
    return v;
}
__device__ __forceinline__ float warpMax(float v){
    #pragma unroll
    for (int o=16;o;o>>=1) v = fmaxf(v, __shfl_xor_sync(0xffffffffu, v, o));
    return v;
}
__device__ __forceinline__ float lrelu(float x){ return x > 0.f ? x : 0.2f*x; }

__device__ __forceinline__ uint32_t smem_u32(const void* p){
    uint32_t a;
    asm("{ .reg .u64 t; cvta.to.shared.u64 t, %1; cvt.u32.u64 %0, t; }" : "=r"(a) : "l"(p));
    return a;
}
__device__ __forceinline__ __nv_bfloat16 bflo(float x, __nv_bfloat16 h){
    return __float2bfloat16(x - __bfloat162float(h));
}

// ---------------- W -> bf16 hi/lo ----------------
__global__ void k_wconv(const float* __restrict__ Ws){
    size_t i = (size_t)blockIdx.x*256 + threadIdx.x;
    if (i >= (size_t)3*HH*HH) return;
    float w = Ws[i];
    __nv_bfloat16 h = __float2bfloat16(w);
    g_Wh[i] = h;
    g_Wl[i] = bflo(w, h);
}

// ---------------- zero alpha accumulators (per layer, before GEMM) ----------------
#define ASZ (BATCH*NN*NH)
__global__ void k_zero(){
    int i = blockIdx.x*256 + threadIdx.x;
    if (i < ASZ) g_as[i] = 0.f;
    else if (i < 2*ASZ) g_ad[i-ASZ] = 0.f;
}

// ---------------- concat [text;label;image] -> X0 (+ bf16 hi/lo) ----------------
__global__ void k_concat(const float4* __restrict__ text, const float4* __restrict__ lab,
                         const float4* __restrict__ img)
{
    size_t idx = (size_t)blockIdx.x*blockDim.x + threadIdx.x;
    const size_t total = (size_t)BATCH*NN*H4;
    if (idx >= total) return;
    int b = (int)(idx / (NN*H4));
    int r = (int)(idx % (NN*H4));
    int n = r / H4;
    int k = r % H4;
    float4 v;
    if (n < TT)          v = text[(size_t)b*TT*H4 + (size_t)n*H4 + k];
    else if (n < TT+LL)  v = lab [(size_t)b*LL*H4 + (size_t)(n-TT)*H4 + k];
    else                 v = img [(size_t)b*II*H4 + (size_t)(n-TT-LL)*H4 + k];
    ((float4*)g_X[0])[idx] = v;
    __nv_bfloat16 hx=__float2bfloat16(v.x), hy=__float2bfloat16(v.y);
    __nv_bfloat16 hz=__float2bfloat16(v.z), hw=__float2bfloat16(v.w);
    ((__nv_bfloat162*)g_Ahi)[2*idx]   = __halves2bfloat162(hx,hy);
    ((__nv_bfloat162*)g_Ahi)[2*idx+1] = __halves2bfloat162(hz,hw);
    ((__nv_bfloat162*)g_Alo)[2*idx]   = __halves2bfloat162(bflo(v.x,hx), bflo(v.y,hy));
    ((__nv_bfloat162*)g_Alo)[2*idx+1] = __halves2bfloat162(bflo(v.z,hz), bflo(v.w,hw));
}

// ---------------- dynamic edges ----------------
__global__ void k_excl(const float* __restrict__ text, const float* __restrict__ lab,
                       const float* __restrict__ img)
{
    __shared__ float sh[8*HH];
    __shared__ float sinv[8];
    int b = blockIdx.x;
    int tid = threadIdx.x;
    for (int i=tid;i<LL*HH;i+=blockDim.x) sh[i]       = lab[(size_t)b*LL*HH + i];
    for (int i=tid;i<II*HH;i+=blockDim.x) sh[LL*HH+i] = img[(size_t)b*II*HH + i];
    __syncthreads();
    int wid = tid>>5, lane = tid&31;
    if (wid < 8){
        float s=0.f;
        for (int k=lane;k<HH;k+=32){ float v=sh[wid*HH+k]; s+=v*v; }
        s = warpSum(s);
        if (lane==0) sinv[wid] = 1.f / fmaxf(sqrtf(s), 1e-8f);
    }
    __syncthreads();
    for (int t=wid;t<TT;t+=8){
        const float* xr = text + (size_t)b*TT*HH + (size_t)t*HH;
        float d0=0,d1=0,d2=0,d3=0,d4=0,d5=0,d6=0,d7=0;
        for (int k=lane;k<HH;k+=32){
            float x = xr[k];
            d0+=x*sh[0*HH+k]; d1+=x*sh[1*HH+k]; d2+=x*sh[2*HH+k]; d3+=x*sh[3*HH+k];
            d4+=x*sh[4*HH+k]; d5+=x*sh[5*HH+k]; d6+=x*sh[6*HH+k]; d7+=x*sh[7*HH+k];
        }
        d0=warpSum(d0); d1=warpSum(d1); d2=warpSum(d2); d3=warpSum(d3);
        d4=warpSum(d4); d5=warpSum(d5); d6=warpSum(d6); d7=warpSum(d7);
        if (lane==0){
            float c0=d0*sinv[0], c1=d1*sinv[1], c2=d2*sinv[2], c3=d3*sinv[3];
            int el=0; float bm=c0;
            if (c1<bm){bm=c1;el=1;} if (c2<bm){bm=c2;el=2;} if (c3<bm){bm=c3;el=3;}
            g_excl[0][b*TT+t]=el;
            float e0=d4*sinv[4], e1=d5*sinv[5], e2=d6*sinv[6], e3=d7*sinv[7];
            int ei=0; bm=e0;
            if (e1<bm){bm=e1;ei=1;} if (e2<bm){bm=e2;ei=2;} if (e3<bm){bm=e3;ei=3;}
            g_excl[1][b*TT+t]=ei;
        }
    }
}

// ---------------- mma.sync bf16-split GEMM + fused alpha partials ----------------
// CTA tile 128x128, BK=64, 8 warps (2x4, 64x32 warp tiles), 3-stage cp.async,
// one __syncthreads per chunk, prefetch depth 2 (wait_group 1).
#define BK 64
#define LDSM 72
#define STG_A (128*LDSM*2)            // 18432
#define STG   (2*STG_A)               // 36864
#define GSMEM (3*STG)                 // 110592 -> 2 CTAs/SM

__device__ __forceinline__ void cp16(uint32_t dst, const void* src){
    asm volatile("cp.async.cg.shared.global [%0], [%1], 16;" :: "r"(dst), "l"(src));
}

__global__ void __launch_bounds__(256) k_gemm_mma(int layer,
        const float* __restrict__ aw_s, const float* __restrict__ aw_d)
{
    extern __shared__ __align__(16) char dsm[];
    uint32_t smem = smem_u32(dsm);
    int tid = threadIdx.x, lane = tid&31, wid = tid>>5;
    int warp_m = (wid&1)*64;
    int warp_n = (wid>>1)*32;

    const __nv_bfloat16* Wb  = g_Wh + (size_t)layer*HH*HH;
    const __nv_bfloat16* Wlb = g_Wl + (size_t)layer*HH*HH;
    size_t arow0 = (size_t)blockIdx.x*128;
    size_t brow0 = (size_t)blockIdx.y*128;

    float acc[4][4][4];
    #pragma unroll
    for (int mi=0;mi<4;mi++)
        #pragma unroll
        for (int nj=0;nj<4;nj++)
            #pragma unroll
            for (int r=0;r<4;r++) acc[mi][nj][r]=0.f;

    auto issue = [&](int c, int s){
        const __nv_bfloat16* Asrc = (c<24)? g_Ahi : g_Alo;
        const __nv_bfloat16* Bsrc = (c<12)? Wb : ((c<24)? Wlb : Wb);
        int col = (c%12)*BK;
        uint32_t sa  = smem + s*STG;
        uint32_t sbm = smem + s*STG + STG_A;
        #pragma unroll
        for (int i=0;i<4;i++){
            int idx = tid + i*256;
            int r = idx>>3, q = idx&7;
            cp16(sa + (uint32_t)(r*LDSM + q*8)*2,
                 Asrc + (arow0 + r)*HH + col + q*8);
        }
        #pragma unroll
        for (int i=0;i<4;i++){
            int idx = tid + i*256;
            int r = idx>>3, q = idx&7;
            cp16(sbm + (uint32_t)(r*LDSM + q*8)*2,
                 Bsrc + (brow0 + r)*HH + col + q*8);
        }
        asm volatile("cp.async.commit_group;" ::: "memory");
    };

    issue(0,0);
    issue(1,1);

    for (int c=0;c<KCH;c++){
        int s = c%3;
        if (c+1 < KCH) asm volatile("cp.async.wait_group 1;" ::: "memory");
        else           asm volatile("cp.async.wait_group 0;" ::: "memory");
        __syncthreads();                       // stage s ready; stage (c+2)%3 free
        if (c+2 < KCH) issue(c+2, (c+2)%3);

        uint32_t saA = smem + s*STG;
        uint32_t saB = smem + s*STG + STG_A;
        #pragma unroll
        for (int ks=0;ks<4;ks++){
            int kb = ks*16;
            uint32_t aF[4][4];
            uint32_t bF[4][2];
            #pragma unroll
            for (int mi=0;mi<4;mi++){
                int row = warp_m + mi*16 + (lane&15);
                int col = kb + ((lane>>4)<<3);
                uint32_t ad = saA + (uint32_t)(row*LDSM + col)*2;
                asm volatile("ldmatrix.sync.aligned.m8n8.x4.shared.b16 {%0,%1,%2,%3}, [%4];"
                    : "=r"(aF[mi][0]), "=r"(aF[mi][1]), "=r"(aF[mi][2]), "=r"(aF[mi][3])
                    : "r"(ad));
            }
            #pragma unroll
            for (int ng=0;ng<2;ng++){
                int n = warp_n + ng*16 + (lane&7) + ((lane>>4)<<3);
                int k = kb + (((lane>>3)&1)<<3);
                uint32_t ad = saB + (uint32_t)(n*LDSM + k)*2;
                uint32_t r0,r1,r2,r3;
                asm volatile("ldmatrix.sync.aligned.m8n8.x4.shared.b16 {%0,%1,%2,%3}, [%4];"
                    : "=r"(r0), "=r"(r1), "=r"(r2), "=r"(r3) : "r"(ad));
                bF[ng*2+0][0]=r0; bF[ng*2+0][1]=r1;
                bF[ng*2+1][0]=r2; bF[ng*2+1][1]=r3;
            }
            #pragma unroll
            for (int mi=0;mi<4;mi++)
                #pragma unroll
                for (int nj=0;nj<4;nj++){
                    asm volatile(
                        "mma.sync.aligned.m16n8k16.row.col.f32.bf16.bf16.f32 "
                        "{%0,%1,%2,%3}, {%4,%5,%6,%7}, {%8,%9}, {%0,%1,%2,%3};"
                        : "+f"(acc[mi][nj][0]), "+f"(acc[mi][nj][1]),
                          "+f"(acc[mi][nj][2]), "+f"(acc[mi][nj][3])
                        : "r"(aF[mi][0]), "r"(aF[mi][1]), "r"(aF[mi][2]), "r"(aF[mi][3]),
                          "r"(bF[nj][0]), "r"(bF[nj][1]));
                }
        }
    }

    // ---- epilogue: write H, and fused alpha partials (32 cols never cross a head) ----
    int g = lane>>2, t2 = (lane&3)*2;
    int cb = (int)brow0 + warp_n;
    int head = cb / DOUT;
    float asv[8], adv2[8];
    #pragma unroll
    for (int nj=0;nj<4;nj++){
        int c = cb + nj*8 + t2;
        asv[nj*2]   = aw_s[c];  asv[nj*2+1]  = aw_s[c+1];
        adv2[nj*2]  = aw_d[c];  adv2[nj*2+1] = aw_d[c+1];
    }
    #pragma unroll
    for (int mi=0;mi<4;mi++){
        size_t row = arow0 + warp_m + mi*16 + g;
        float* cr0 = g_H + row*HH + cb;
        float* cr1 = g_H + (row+8)*HH + cb;
        float s0=0.f,d0=0.f,s1=0.f,d1=0.f;
        #pragma unroll
        for (int nj=0;nj<4;nj++){
            int col = nj*8 + t2;
            *(float2*)(cr0 + col) = make_float2(acc[mi][nj][0], acc[mi][nj][1]);
            *(float2*)(cr1 + col) = make_float2(acc[mi][nj][2], acc[mi][nj][3]);
            s0 += acc[mi][nj][0]*asv[nj*2] + acc[mi][nj][1]*asv[nj*2+1];
            d0 += acc[mi][nj][0]*adv2[nj*2] + acc[mi][nj][1]*adv2[nj*2+1];
            s1 += acc[mi][nj][2]*asv[nj*2] + acc[mi][nj][3]*asv[nj*2+1];
            d1 += acc[mi][nj][2]*adv2[nj*2] + acc[mi][nj][3]*adv2[nj*2+1];
        }
        // quad reduce (lanes sharing a row: lane&3)
        s0 += __shfl_xor_sync(0xffffffffu, s0, 1); s0 += __shfl_xor_sync(0xffffffffu, s0, 2);
        d0 += __shfl_xor_sync(0xffffffffu, d0, 1); d0 += __shfl_xor_sync(0xffffffffu, d0, 2);
        s1 += __shfl_xor_sync(0xffffffffu, s1, 1); s1 += __shfl_xor_sync(0xffffffffu, s1, 2);
        d1 += __shfl_xor_sync(0xffffffffu, d1, 1); d1 += __shfl_xor_sync(0xffffffffu, d1, 2);
        if ((lane&3)==0){
            atomicAdd(&g_as[row*NH + head], s0);
            atomicAdd(&g_ad[row*NH + head], d0);
            atomicAdd(&g_as[(row+8)*NH + head], s1);
            atomicAdd(&g_ad[(row+8)*NH + head], d1);
        }
    }
}

// ---------------- text dsts: one warp per (b,t); heavy rows staged in smem ----------
__global__ void __launch_bounds__(256) k_text(int cur, const float* __restrict__ bias,
        const float* __restrict__ gamma, const float* __restrict__ beta,
        float* __restrict__ outp, int isLast)
{
    __shared__ float s_h[8*HH];    // 8 heavy H rows (24KB)
    __shared__ float s_as[32];     // heavy as values
    int tid = threadIdx.x;
    int lane = tid & 31;
    int b = blockIdx.x >> 6;       // 64 blocks per batch
    size_t nbase = (size_t)b*NN;

    {
        const float4* hs = (const float4*)(g_H + (nbase + TT)*HH);
        #pragma unroll
        for (int i=0;i<6;i++) ((float4*)s_h)[tid + i*256] = hs[tid + i*256];
        if (tid < 32) s_as[tid] = g_as[(nbase + TT)*NH + tid];
    }
    __syncthreads();

    int gw = blockIdx.x*8 + (tid>>5);
    int t = gw % TT;
    const float* Xcur = g_X[cur];
    float* dst; size_t drow;
    if (isLast){ dst = outp;       drow = ((size_t)b*TT + t)*HH; }
    else       { dst = g_X[cur^1]; drow = (nbase + t)*HH; }

    int el = g_excl[0][b*TT+t], ei = g_excl[1][b*TT+t];
    int srcs[9];
    srcs[0]=t;
    srcs[1]=(t>0)? t-1 : t;
    srcs[2]=(t<TT-1)? t+1 : t;
    srcs[3]=0 + (0>=el);
    srcs[4]=1 + (1>=el);
    srcs[5]=2 + (2>=el);
    srcs[6]=LL + 0 + (0>=ei);
    srcs[7]=LL + 1 + (1>=ei);
    srcs[8]=LL + 2 + (2>=ei);
    bool valid1 = (t>0), valid2 = (t<TT-1);

    float4 adv = ((const float4*)g_ad)[nbase + t];
    float adh[4] = {adv.x, adv.y, adv.z, adv.w};
    float w[9][4];
    float mx[4] = {-1e30f,-1e30f,-1e30f,-1e30f};
    #pragma unroll
    for (int e=0;e<9;e++){
        float4 av;
        if (e < 3) av = ((const float4*)g_as)[nbase + srcs[e]];
        else       av = *(const float4*)&s_as[srcs[e]*4];
        float a[4] = {av.x,av.y,av.z,av.w};
        bool v = (e==1)? valid1 : ((e==2)? valid2 : true);
        #pragma unroll
        for (int h=0;h<4;h++){
            float ev = lrelu(a[h] + adh[h]);
            ev = v ? ev : -1e30f;
            w[e][h]=ev;
            mx[h]=fmaxf(mx[h],ev);
        }
    }
    float den[4]={0,0,0,0};
    #pragma unroll
    for (int e=0;e<9;e++)
        #pragma unroll
        for (int h=0;h<4;h++){ float ex=expf(w[e][h]-mx[h]); w[e][h]=ex; den[h]+=ex; }
    #pragma unroll
    for (int h=0;h<4;h++) den[h] = 1.f/(den[h]+1e-16f);
    #pragma unroll
    for (int e=0;e<9;e++)
        #pragma unroll
        for (int h=0;h<4;h++) w[e][h]*=den[h];

    float acc[24];
    #pragma unroll
    for (int i=0;i<24;i++) acc[i]=0.f;
    const float* Hb = g_H + nbase*HH;
    #pragma unroll
    for (int e=0;e<3;e++){
        const float* hr = Hb + (size_t)srcs[e]*HH + lane;
        #pragma unroll
        for (int i=0;i<24;i++) acc[i] += w[e][i/6]*hr[32*i];
    }
    #pragma unroll
    for (int e=3;e<9;e++){
        const float* hr = s_h + srcs[e]*HH + lane;
        #pragma unroll
        for (int i=0;i<24;i++) acc[i] += w[e][i/6]*hr[32*i];
    }
    const float* xr = Xcur + (nbase + t)*HH + lane;
    float s=0.f;
    #pragma unroll
    for (int i=0;i<24;i++){
        int c = lane + 32*i;
        float v = fmaxf(acc[i] + bias[c], 0.f) + xr[32*i];
        acc[i]=v; s+=v;
    }
    s = warpSum(s);
    float mean = s*(1.f/HH);
    float q=0.f;
    #pragma unroll
    for (int i=0;i<24;i++){ float dd=acc[i]-mean; q+=dd*dd; }
    q = warpSum(q);
    float rstd = rsqrtf(q*(1.f/HH)+1e-5f);
    if (isLast){
        #pragma unroll
        for (int i=0;i<24;i++){
            int c = lane+32*i;
            dst[drow + c] = (acc[i]-mean)*rstd*gamma[c] + beta[c];
        }
    } else {
        #pragma unroll
        for (int i=0;i<24;i++){
            int c = lane+32*i;
            float o = (acc[i]-mean)*rstd*gamma[c] + beta[c];
            dst[drow + c] = o;
            __nv_bfloat16 h = __float2bfloat16(o);
            g_Ahi[drow + c] = h;
            g_Alo[drow + c] = bflo(o, h);
        }
    }
}

// ---------------- heavy dsts: ONE block per batch handles all 8 dsts ----------
#define HV_WSZ (520*40)
__global__ void __launch_bounds__(768) k_heavy2(int cur, const float* __restrict__ bias,
        const float* __restrict__ gamma, const float* __restrict__ beta)
{
    extern __shared__ float s_wt[];          // HV_WSZ floats
    __shared__ float s_mx[4];
    __shared__ float s_redm[17*4];
    __shared__ float s_redd[17*4];
    __shared__ float s_dinv[32];             // [d*4+h]
    __shared__ float s_red[24], s_red2[24];
    __shared__ float s_stats[2];

    int b = blockIdx.x;
    int tid = threadIdx.x, wid = tid>>5, lane = tid&31;
    size_t nbase = (size_t)b*NN;

    for (int d=0; d<8; d++){
        int dl = d&3;
        const int* excl = g_excl[d>>2] + b*TT;
        float4 adv = ((const float4*)g_ad)[nbase + TT + d];
        float e0=-1e30f, e1=-1e30f, e2=-1e30f, e3=-1e30f;
        if (tid < NN){
            bool v = (tid >= TT) || (excl[tid] != dl);
            float4 av = ((const float4*)g_as)[nbase + tid];
            if (v){
                e0 = lrelu(av.x + adv.x);
                e1 = lrelu(av.y + adv.y);
                e2 = lrelu(av.z + adv.z);
                e3 = lrelu(av.w + adv.w);
            }
        }
        if (wid < 17){
            float m0=warpMax(e0), m1=warpMax(e1), m2=warpMax(e2), m3=warpMax(e3);
            if (lane==0){ s_redm[wid*4+0]=m0; s_redm[wid*4+1]=m1; s_redm[wid*4+2]=m2; s_redm[wid*4+3]=m3; }
        }
        __syncthreads();
        if (tid < 4){
            float m=-1e30f;
            #pragma unroll
            for (int wg=0; wg<17; wg++) m = fmaxf(m, s_redm[wg*4+tid]);
            s_mx[tid] = m;
        }
        __syncthreads();
        float x0=0.f,x1=0.f,x2=0.f,x3=0.f;
        if (tid < NN){
            x0 = expf(e0 - s_mx[0]);
            x1 = expf(e1 - s_mx[1]);
            x2 = expf(e2 - s_mx[2]);
            x3 = expf(e3 - s_mx[3]);
            s_wt[tid*40 + 0*8 + d] = x0;
            s_wt[tid*40 + 1*8 + d] = x1;
            s_wt[tid*40 + 2*8 + d] = x2;
            s_wt[tid*40 + 3*8 + d] = x3;
        }
        if (wid < 17){
            float d0=warpSum(x0), d1=warpSum(x1), d2=warpSum(x2), d3=warpSum(x3);
            if (lane==0){ s_redd[wid*4+0]=d0; s_redd[wid*4+1]=d1; s_redd[wid*4+2]=d2; s_redd[wid*4+3]=d3; }
        }
        __syncthreads();
        if (tid < 4){
            float sm=0.f;
            #pragma unroll
            for (int wg=0; wg<17; wg++) sm += s_redd[wg*4+tid];
            s_dinv[d*4+tid] = 1.f/(sm + 1e-16f);
        }
        __syncthreads();
    }

    int c = tid;
    int h = c / DOUT;
    const float* Hb = g_H + nbase*HH;
    float a[8];
    #pragma unroll
    for (int d=0;d<8;d++) a[d]=0.f;
    for (int t=0; t<NN; t++){
        float hr = Hb[(size_t)t*HH + c];
        float4 w0 = *(const float4*)&s_wt[t*40 + h*8];
        float4 w1 = *(const float4*)&s_wt[t*40 + h*8 + 4];
        a[0] += w0.x*hr; a[1] += w0.y*hr; a[2] += w0.z*hr; a[3] += w0.w*hr;
        a[4] += w1.x*hr; a[5] += w1.y*hr; a[6] += w1.z*hr; a[7] += w1.w*hr;
    }
    float y[8];
    float bi = bias[c];
    #pragma unroll
    for (int d=0;d<8;d++){
        float agg = a[d]*s_dinv[d*4+h];
        y[d] = fmaxf(agg + bi, 0.f) + g_X[cur][(nbase + TT + d)*HH + c];
    }

    float gm = gamma[c], bt = beta[c];
    for (int d=0;d<8;d++){
        float ps = warpSum(y[d]);
        float pq = warpSum(y[d]*y[d]);
        if (lane==0){ s_red[wid]=ps; s_red2[wid]=pq; }
        __syncthreads();
        if (tid==0){
            float S=0.f,Q=0.f;
            #pragma unroll
            for (int wg=0;wg<24;wg++){ S+=s_red[wg]; Q+=s_red2[wg]; }
            float mean = S*(1.f/HH);
            float var  = Q*(1.f/HH) - mean*mean;
            s_stats[0]=mean;
            s_stats[1]=rsqrtf(fmaxf(var,0.f)+1e-5f);
        }
        __syncthreads();
        float mean=s_stats[0], rstd=s_stats[1];
        size_t row = (nbase + TT + d)*HH;
        float o = (y[d]-mean)*rstd*gm + bt;
        g_X[cur^1][row + c] = o;
        __nv_bfloat16 hh = __float2bfloat16(o);
        g_Ahi[row + c] = hh;
        g_Alo[row + c] = bflo(o, hh);
    }
}

// ---------------- launch ----------------
extern "C" void kernel_launch(void* const* d_in, const int* in_sizes, int n_in,
                              void* d_out, int out_size)
{
    const float* text = (const float*)d_in[0];
    const float* lab  = (const float*)d_in[1];
    const float* img  = (const float*)d_in[2];
    const float* Ws   = (const float*)d_in[3];
    const float* aws  = (const float*)d_in[4];
    const float* awd  = (const float*)d_in[5];
    const float* bias = (const float*)d_in[6];
    const float* gam  = (const float*)d_in[7];
    const float* bet  = (const float*)d_in[8];
    float* outp = (float*)d_out;

    cudaFuncSetAttribute(k_gemm_mma, cudaFuncAttributeMaxDynamicSharedMemorySize, GSMEM);
    cudaFuncSetAttribute(k_heavy2, cudaFuncAttributeMaxDynamicSharedMemorySize, HV_WSZ*4);

    k_wconv<<<(3*HH*HH + 255)/256, 256>>>(Ws);
    {
        size_t total = (size_t)BATCH*NN*H4;
        int blocks = (int)((total + 255)/256);
        k_concat<<<blocks,256>>>((const float4*)text,(const float4*)lab,(const float4*)img);
    }
    k_excl<<<BATCH,256>>>(text, lab, img);

    int cur = 0;
    for (int l=0;l<3;l++){
        k_zero<<<(2*ASZ + 255)/256, 256>>>();
        k_gemm_mma<<<dim3((BATCH*NN)/128, HH/128), 256, GSMEM>>>(l, aws + l*HH, awd + l*HH);
        int last = (l==2);
        k_text<<<(BATCH*TT)/8,256>>>(cur, bias+l*HH, gam+l*HH, bet+l*HH, outp, last);
        if (!last) k_heavy2<<<BATCH, 768, HV_WSZ*4>>>(cur, bias+l*HH, gam+l*HH, bet+l*HH);
        cur ^= 1;
    }
}

// round 10
// speedup vs baseline: 1.8169x; 1.0026x over previous
#include <cuda_runtime.h>
#include <cuda_bf16.h>
#include <math.h>
#include <stdint.h>

#define BATCH 64
#define TT 512
#define LL 4
#define II 4
#define NN 520          // TT+LL+II
#define HH 768
#define NH 4
#define DOUT 192
#define H4 (HH/4)
#define KCH 36          // 36 K-chunks of 64 (hi,hi,lo x 12)

// ---------------- scratch (device globals; no allocations allowed) ----------------
__device__ float g_X[2][(size_t)BATCH*NN*HH];   // ping-pong node features (fp32 residual path)
__device__ float g_H[(size_t)BATCH*NN*HH];      // h = X @ W^T
__device__ float g_as[BATCH*NN*NH];             // (h*a_s).sum(-1)
__device__ float g_ad[BATCH*NN*NH];             // (h*a_d).sum(-1)
__device__ int   g_excl[2][BATCH*TT];           // [0]=excluded label idx, [1]=excluded image idx
__device__ __nv_bfloat16 g_Ahi[(size_t)BATCH*NN*HH];  // bf16 hi(X)
__device__ __nv_bfloat16 g_Alo[(size_t)BATCH*NN*HH];  // bf16 lo(X)
__device__ __nv_bfloat16 g_Wh[(size_t)3*HH*HH];       // bf16 hi(W)
__device__ __nv_bfloat16 g_Wl[(size_t)3*HH*HH];       // bf16 lo(W)

__device__ __forceinline__ float warpSum(float v){
    #pragma unroll
    for (int o=16;o;o>>=1) v += __shfl_xor_sync(0xffffffffu, v, o);
    return v;
}
__device__ __forceinline__ float warpMax(float v){
    #pragma unroll
    for (int o=16;o;o>>=1) v = fmaxf(v, __shfl_xor_sync(0xffffffffu, v, o));
    return v;
}
__device__ __forceinline__ float lrelu(float x){ return x > 0.f ? x : 0.2f*x; }

__device__ __forceinline__ uint32_t smem_u32(const void* p){
    uint32_t a;
    asm("{ .reg .u64 t; cvta.to.shared.u64 t, %1; cvt.u32.u64 %0, t; }" : "=r"(a) : "l"(p));
    return a;
}
__device__ __forceinline__ __nv_bfloat16 bflo(float x, __nv_bfloat16 h){
    return __float2bfloat16(x - __bfloat162float(h));
}

// ---------------- W -> bf16 hi/lo ----------------
__global__ void k_wconv(const float* __restrict__ Ws){
    size_t i = (size_t)blockIdx.x*256 + threadIdx.x;
    if (i >= (size_t)3*HH*HH) return;
    float w = Ws[i];
    __nv_bfloat16 h = __float2bfloat16(w);
    g_Wh[i] = h;
    g_Wl[i] = bflo(w, h);
}

// ---------------- zero alpha accumulators (per layer, before GEMM) ----------------
#define ASZ (BATCH*NN*NH)
__global__ void k_zero(){
    int i = blockIdx.x*256 + threadIdx.x;
    if (i < ASZ) g_as[i] = 0.f;
    else if (i < 2*ASZ) g_ad[i-ASZ] = 0.f;
}

// ---------------- concat [text;label;image] -> X0 (+ bf16 hi/lo) ----------------
__global__ void k_concat(const float4* __restrict__ text, const float4* __restrict__ lab,
                         const float4* __restrict__ img)
{
    size_t idx = (size_t)blockIdx.x*blockDim.x + threadIdx.x;
    const size_t total = (size_t)BATCH*NN*H4;
    if (idx >= total) return;
    int b = (int)(idx / (NN*H4));
    int r = (int)(idx % (NN*H4));
    int n = r / H4;
    int k = r % H4;
    float4 v;
    if (n < TT)          v = text[(size_t)b*TT*H4 + (size_t)n*H4 + k];
    else if (n < TT+LL)  v = lab [(size_t)b*LL*H4 + (size_t)(n-TT)*H4 + k];
    else                 v = img [(size_t)b*II*H4 + (size_t)(n-TT-LL)*H4 + k];
    ((float4*)g_X[0])[idx] = v;
    __nv_bfloat16 hx=__float2bfloat16(v.x), hy=__float2bfloat16(v.y);
    __nv_bfloat16 hz=__float2bfloat16(v.z), hw=__float2bfloat16(v.w);
    ((__nv_bfloat162*)g_Ahi)[2*idx]   = __halves2bfloat162(hx,hy);
    ((__nv_bfloat162*)g_Ahi)[2*idx+1] = __halves2bfloat162(hz,hw);
    ((__nv_bfloat162*)g_Alo)[2*idx]   = __halves2bfloat162(bflo(v.x,hx), bflo(v.y,hy));
    ((__nv_bfloat162*)g_Alo)[2*idx+1] = __halves2bfloat162(bflo(v.z,hz), bflo(v.w,hw));
}

// ---------------- dynamic edges ----------------
__global__ void k_excl(const float* __restrict__ text, const float* __restrict__ lab,
                       const float* __restrict__ img)
{
    __shared__ float sh[8*HH];
    __shared__ float sinv[8];
    int b = blockIdx.x;
    int tid = threadIdx.x;
    for (int i=tid;i<LL*HH;i+=blockDim.x) sh[i]       = lab[(size_t)b*LL*HH + i];
    for (int i=tid;i<II*HH;i+=blockDim.x) sh[LL*HH+i] = img[(size_t)b*II*HH + i];
    __syncthreads();
    int wid = tid>>5, lane = tid&31;
    if (wid < 8){
        float s=0.f;
        for (int k=lane;k<HH;k+=32){ float v=sh[wid*HH+k]; s+=v*v; }
        s = warpSum(s);
        if (lane==0) sinv[wid] = 1.f / fmaxf(sqrtf(s), 1e-8f);
    }
    __syncthreads();
    for (int t=wid;t<TT;t+=8){
        const float* xr = text + (size_t)b*TT*HH + (size_t)t*HH;
        float d0=0,d1=0,d2=0,d3=0,d4=0,d5=0,d6=0,d7=0;
        for (int k=lane;k<HH;k+=32){
            float x = xr[k];
            d0+=x*sh[0*HH+k]; d1+=x*sh[1*HH+k]; d2+=x*sh[2*HH+k]; d3+=x*sh[3*HH+k];
            d4+=x*sh[4*HH+k]; d5+=x*sh[5*HH+k]; d6+=x*sh[6*HH+k]; d7+=x*sh[7*HH+k];
        }
        d0=warpSum(d0); d1=warpSum(d1); d2=warpSum(d2); d3=warpSum(d3);
        d4=warpSum(d4); d5=warpSum(d5); d6=warpSum(d6); d7=warpSum(d7);
        if (lane==0){
            float c0=d0*sinv[0], c1=d1*sinv[1], c2=d2*sinv[2], c3=d3*sinv[3];
            int el=0; float bm=c0;
            if (c1<bm){bm=c1;el=1;} if (c2<bm){bm=c2;el=2;} if (c3<bm){bm=c3;el=3;}
            g_excl[0][b*TT+t]=el;
            float e0=d4*sinv[4], e1=d5*sinv[5], e2=d6*sinv[6], e3=d7*sinv[7];
            int ei=0; bm=e0;
            if (e1<bm){bm=e1;ei=1;} if (e2<bm){bm=e2;ei=2;} if (e3<bm){bm=e3;ei=3;}
            g_excl[1][b*TT+t]=ei;
        }
    }
}

// ---------------- mma.sync bf16-split GEMM + fused alpha partials ----------------
// CTA tile 128x128, 4 warps (2x2 of 64x64 warp tiles), BK=64, 3-stage cp.async,
// one __syncthreads per chunk. 128 threads -> up to 256 regs, 2 CTAs/SM.
#define BK 64
#define LDSM 72
#define STG_A (128*LDSM*2)            // 18432
#define STG   (2*STG_A)               // 36864
#define GSMEM (3*STG)                 // 110592 -> 2 CTAs/SM

__device__ __forceinline__ void cp16(uint32_t dst, const void* src){
    asm volatile("cp.async.cg.shared.global [%0], [%1], 16;" :: "r"(dst), "l"(src));
}

__global__ void __launch_bounds__(128,2) k_gemm_mma(int layer,
        const float* __restrict__ aw_s, const float* __restrict__ aw_d)
{
    extern __shared__ __align__(16) char dsm[];
    uint32_t smem = smem_u32(dsm);
    int tid = threadIdx.x, lane = tid&31, wid = tid>>5;
    int warp_m = (wid&1)*64;
    int warp_n = (wid>>1)*64;

    const __nv_bfloat16* Wb  = g_Wh + (size_t)layer*HH*HH;
    const __nv_bfloat16* Wlb = g_Wl + (size_t)layer*HH*HH;
    size_t arow0 = (size_t)blockIdx.x*128;
    size_t brow0 = (size_t)blockIdx.y*128;

    float acc[4][8][4];
    #pragma unroll
    for (int mi=0;mi<4;mi++)
        #pragma unroll
        for (int nj=0;nj<8;nj++)
            #pragma unroll
            for (int r=0;r<4;r++) acc[mi][nj][r]=0.f;

    auto issue = [&](int c, int s){
        const __nv_bfloat16* Asrc = (c<24)? g_Ahi : g_Alo;
        const __nv_bfloat16* Bsrc = (c<12)? Wb : ((c<24)? Wlb : Wb);
        int col = (c%12)*BK;
        uint32_t sa  = smem + s*STG;
        uint32_t sbm = smem + s*STG + STG_A;
        #pragma unroll
        for (int i=0;i<8;i++){                 // A: 128 rows x 8 uint4, 128 threads
            int idx = tid + i*128;
            int r = idx>>3, q = idx&7;
            cp16(sa + (uint32_t)(r*LDSM + q*8)*2,
                 Asrc + (arow0 + r)*HH + col + q*8);
        }
        #pragma unroll
        for (int i=0;i<8;i++){
            int idx = tid + i*128;
            int r = idx>>3, q = idx&7;
            cp16(sbm + (uint32_t)(r*LDSM + q*8)*2,
                 Bsrc + (brow0 + r)*HH + col + q*8);
        }
        asm volatile("cp.async.commit_group;" ::: "memory");
    };

    issue(0,0);
    issue(1,1);

    for (int c=0;c<KCH;c++){
        int s = c%3;
        if (c+1 < KCH) asm volatile("cp.async.wait_group 1;" ::: "memory");
        else           asm volatile("cp.async.wait_group 0;" ::: "memory");
        __syncthreads();                       // stage s ready; stage (c+2)%3 free
        if (c+2 < KCH) issue(c+2, (c+2)%3);

        uint32_t saA = smem + s*STG;
        uint32_t saB = smem + s*STG + STG_A;
        #pragma unroll
        for (int ks=0;ks<4;ks++){
            int kb = ks*16;
            uint32_t aF[4][4];
            uint32_t bF[8][2];
            #pragma unroll
            for (int mi=0;mi<4;mi++){
                int row = warp_m + mi*16 + (lane&15);
                int col = kb + ((lane>>4)<<3);
                uint32_t ad = saA + (uint32_t)(row*LDSM + col)*2;
                asm volatile("ldmatrix.sync.aligned.m8n8.x4.shared.b16 {%0,%1,%2,%3}, [%4];"
                    : "=r"(aF[mi][0]), "=r"(aF[mi][1]), "=r"(aF[mi][2]), "=r"(aF[mi][3])
                    : "r"(ad));
            }
            #pragma unroll
            for (int ng=0;ng<4;ng++){
                int n = warp_n + ng*16 + (lane&7) + ((lane>>4)<<3);
                int k = kb + (((lane>>3)&1)<<3);
                uint32_t ad = saB + (uint32_t)(n*LDSM + k)*2;
                uint32_t r0,r1,r2,r3;
                asm volatile("ldmatrix.sync.aligned.m8n8.x4.shared.b16 {%0,%1,%2,%3}, [%4];"
                    : "=r"(r0), "=r"(r1), "=r"(r2), "=r"(r3) : "r"(ad));
                bF[ng*2+0][0]=r0; bF[ng*2+0][1]=r1;
                bF[ng*2+1][0]=r2; bF[ng*2+1][1]=r3;
            }
            #pragma unroll
            for (int mi=0;mi<4;mi++)
                #pragma unroll
                for (int nj=0;nj<8;nj++){
                    asm volatile(
                        "mma.sync.aligned.m16n8k16.row.col.f32.bf16.bf16.f32 "
                        "{%0,%1,%2,%3}, {%4,%5,%6,%7}, {%8,%9}, {%0,%1,%2,%3};"
                        : "+f"(acc[mi][nj][0]), "+f"(acc[mi][nj][1]),
                          "+f"(acc[mi][nj][2]), "+f"(acc[mi][nj][3])
                        : "r"(aF[mi][0]), "r"(aF[mi][1]), "r"(aF[mi][2]), "r"(aF[mi][3]),
                          "r"(bF[nj][0]), "r"(bF[nj][1]));
                }
        }
    }

    // ---- epilogue: write H + fused alpha partials ----
    // 64-col warp block lies within one head (192 = 3*64).
    int g = lane>>2, t2 = (lane&3)*2;
    int cb = (int)brow0 + warp_n;
    int head = cb / DOUT;
    float asv[16], adv2[16];
    #pragma unroll
    for (int nj=0;nj<8;nj++){
        int c = cb + nj*8 + t2;
        asv[nj*2]   = aw_s[c];  asv[nj*2+1]  = aw_s[c+1];
        adv2[nj*2]  = aw_d[c];  adv2[nj*2+1] = aw_d[c+1];
    }
    #pragma unroll
    for (int mi=0;mi<4;mi++){
        size_t row = arow0 + warp_m + mi*16 + g;
        float* cr0 = g_H + row*HH + cb;
        float* cr1 = g_H + (row+8)*HH + cb;
        float s0=0.f,d0=0.f,s1=0.f,d1=0.f;
        #pragma unroll
        for (int nj=0;nj<8;nj++){
            int col = nj*8 + t2;
            *(float2*)(cr0 + col) = make_float2(acc[mi][nj][0], acc[mi][nj][1]);
            *(float2*)(cr1 + col) = make_float2(acc[mi][nj][2], acc[mi][nj][3]);
            s0 += acc[mi][nj][0]*asv[nj*2] + acc[mi][nj][1]*asv[nj*2+1];
            d0 += acc[mi][nj][0]*adv2[nj*2] + acc[mi][nj][1]*adv2[nj*2+1];
            s1 += acc[mi][nj][2]*asv[nj*2] + acc[mi][nj][3]*asv[nj*2+1];
            d1 += acc[mi][nj][2]*adv2[nj*2] + acc[mi][nj][3]*adv2[nj*2+1];
        }
        s0 += __shfl_xor_sync(0xffffffffu, s0, 1); s0 += __shfl_xor_sync(0xffffffffu, s0, 2);
        d0 += __shfl_xor_sync(0xffffffffu, d0, 1); d0 += __shfl_xor_sync(0xffffffffu, d0, 2);
        s1 += __shfl_xor_sync(0xffffffffu, s1, 1); s1 += __shfl_xor_sync(0xffffffffu, s1, 2);
        d1 += __shfl_xor_sync(0xffffffffu, d1, 1); d1 += __shfl_xor_sync(0xffffffffu, d1, 2);
        if ((lane&3)==0){
            atomicAdd(&g_as[row*NH + head], s0);
            atomicAdd(&g_ad[row*NH + head], d0);
            atomicAdd(&g_as[(row+8)*NH + head], s1);
            atomicAdd(&g_ad[(row+8)*NH + head], d1);
        }
    }
}

// ---------------- text dsts: one warp per (b,t); heavy rows staged in smem ----------
__global__ void __launch_bounds__(256) k_text(int cur, const float* __restrict__ bias,
        const float* __restrict__ gamma, const float* __restrict__ beta,
        float* __restrict__ outp, int isLast)
{
    __shared__ float s_h[8*HH];    // 8 heavy H rows (24KB)
    __shared__ float s_as[32];     // heavy as values
    int tid = threadIdx.x;
    int lane = tid & 31;
    int b = blockIdx.x >> 6;       // 64 blocks per batch
    size_t nbase = (size_t)b*NN;

    {
        const float4* hs = (const float4*)(g_H + (nbase + TT)*HH);
        #pragma unroll
        for (int i=0;i<6;i++) ((float4*)s_h)[tid + i*256] = hs[tid + i*256];
        if (tid < 32) s_as[tid] = g_as[(nbase + TT)*NH + tid];
    }
    __syncthreads();

    int gw = blockIdx.x*8 + (tid>>5);
    int t = gw % TT;
    const float* Xcur = g_X[cur];
    float* dst; size_t drow;
    if (isLast){ dst = outp;       drow = ((size_t)b*TT + t)*HH; }
    else       { dst = g_X[cur^1]; drow = (nbase + t)*HH; }

    int el = g_excl[0][b*TT+t], ei = g_excl[1][b*TT+t];
    int srcs[9];
    srcs[0]=t;
    srcs[1]=(t>0)? t-1 : t;
    srcs[2]=(t<TT-1)? t+1 : t;
    srcs[3]=0 + (0>=el);
    srcs[4]=1 + (1>=el);
    srcs[5]=2 + (2>=el);
    srcs[6]=LL + 0 + (0>=ei);
    srcs[7]=LL + 1 + (1>=ei);
    srcs[8]=LL + 2 + (2>=ei);
    bool valid1 = (t>0), valid2 = (t<TT-1);

    float4 adv = ((const float4*)g_ad)[nbase + t];
    float adh[4] = {adv.x, adv.y, adv.z, adv.w};
    float w[9][4];
    float mx[4] = {-1e30f,-1e30f,-1e30f,-1e30f};
    #pragma unroll
    for (int e=0;e<9;e++){
        float4 av;
        if (e < 3) av = ((const float4*)g_as)[nbase + srcs[e]];
        else       av = *(const float4*)&s_as[srcs[e]*4];
        float a[4] = {av.x,av.y,av.z,av.w};
        bool v = (e==1)? valid1 : ((e==2)? valid2 : true);
        #pragma unroll
        for (int h=0;h<4;h++){
            float ev = lrelu(a[h] + adh[h]);
            ev = v ? ev : -1e30f;
            w[e][h]=ev;
            mx[h]=fmaxf(mx[h],ev);
        }
    }
    float den[4]={0,0,0,0};
    #pragma unroll
    for (int e=0;e<9;e++)
        #pragma unroll
        for (int h=0;h<4;h++){ float ex=expf(w[e][h]-mx[h]); w[e][h]=ex; den[h]+=ex; }
    #pragma unroll
    for (int h=0;h<4;h++) den[h] = 1.f/(den[h]+1e-16f);
    #pragma unroll
    for (int e=0;e<9;e++)
        #pragma unroll
        for (int h=0;h<4;h++) w[e][h]*=den[h];

    float acc[24];
    #pragma unroll
    for (int i=0;i<24;i++) acc[i]=0.f;
    const float* Hb = g_H + nbase*HH;
    #pragma unroll
    for (int e=0;e<3;e++){
        const float* hr = Hb + (size_t)srcs[e]*HH + lane;
        #pragma unroll
        for (int i=0;i<24;i++) acc[i] += w[e][i/6]*hr[32*i];
    }
    #pragma unroll
    for (int e=3;e<9;e++){
        const float* hr = s_h + srcs[e]*HH + lane;
        #pragma unroll
        for (int i=0;i<24;i++) acc[i] += w[e][i/6]*hr[32*i];
    }
    const float* xr = Xcur + (nbase + t)*HH + lane;
    float s=0.f;
    #pragma unroll
    for (int i=0;i<24;i++){
        int c = lane + 32*i;
        float v = fmaxf(acc[i] + bias[c], 0.f) + xr[32*i];
        acc[i]=v; s+=v;
    }
    s = warpSum(s);
    float mean = s*(1.f/HH);
    float q=0.f;
    #pragma unroll
    for (int i=0;i<24;i++){ float dd=acc[i]-mean; q+=dd*dd; }
    q = warpSum(q);
    float rstd = rsqrtf(q*(1.f/HH)+1e-5f);
    if (isLast){
        #pragma unroll
        for (int i=0;i<24;i++){
            int c = lane+32*i;
            dst[drow + c] = (acc[i]-mean)*rstd*gamma[c] + beta[c];
        }
    } else {
        #pragma unroll
        for (int i=0;i<24;i++){
            int c = lane+32*i;
            float o = (acc[i]-mean)*rstd*gamma[c] + beta[c];
            dst[drow + c] = o;
            __nv_bfloat16 h = __float2bfloat16(o);
            g_Ahi[drow + c] = h;
            g_Alo[drow + c] = bflo(o, h);
        }
    }
}

// ---------------- heavy dsts: ONE block per batch handles all 8 dsts ----------
#define HV_WSZ (520*40)
__global__ void __launch_bounds__(768) k_heavy2(int cur, const float* __restrict__ bias,
        const float* __restrict__ gamma, const float* __restrict__ beta)
{
    extern __shared__ float s_wt[];          // HV_WSZ floats
    __shared__ float s_mx[4];
    __shared__ float s_redm[17*4];
    __shared__ float s_redd[17*4];
    __shared__ float s_dinv[32];             // [d*4+h]
    __shared__ float s_red[24], s_red2[24];
    __shared__ float s_stats[2];

    int b = blockIdx.x;
    int tid = threadIdx.x, wid = tid>>5, lane = tid&31;
    size_t nbase = (size_t)b*NN;

    for (int d=0; d<8; d++){
        int dl = d&3;
        const int* excl = g_excl[d>>2] + b*TT;
        float4 adv = ((const float4*)g_ad)[nbase + TT + d];
        float e0=-1e30f, e1=-1e30f, e2=-1e30f, e3=-1e30f;
        if (tid < NN){
            bool v = (tid >= TT) || (excl[tid] != dl);
            float4 av = ((const float4*)g_as)[nbase + tid];
            if (v){
                e0 = lrelu(av.x + adv.x);
                e1 = lrelu(av.y + adv.y);
                e2 = lrelu(av.z + adv.z);
                e3 = lrelu(av.w + adv.w);
            }
        }
        if (wid < 17){
            float m0=warpMax(e0), m1=warpMax(e1), m2=warpMax(e2), m3=warpMax(e3);
            if (lane==0){ s_redm[wid*4+0]=m0; s_redm[wid*4+1]=m1; s_redm[wid*4+2]=m2; s_redm[wid*4+3]=m3; }
        }
        __syncthreads();
        if (tid < 4){
            float m=-1e30f;
            #pragma unroll
            for (int wg=0; wg<17; wg++) m = fmaxf(m, s_redm[wg*4+tid]);
            s_mx[tid] = m;
        }
        __syncthreads();
        float x0=0.f,x1=0.f,x2=0.f,x3=0.f;
        if (tid < NN){
            x0 = expf(e0 - s_mx[0]);
            x1 = expf(e1 - s_mx[1]);
            x2 = expf(e2 - s_mx[2]);
            x3 = expf(e3 - s_mx[3]);
            s_wt[tid*40 + 0*8 + d] = x0;
            s_wt[tid*40 + 1*8 + d] = x1;
            s_wt[tid*40 + 2*8 + d] = x2;
            s_wt[tid*40 + 3*8 + d] = x3;
        }
        if (wid < 17){
            float d0=warpSum(x0), d1=warpSum(x1), d2=warpSum(x2), d3=warpSum(x3);
            if (lane==0){ s_redd[wid*4+0]=d0; s_redd[wid*4+1]=d1; s_redd[wid*4+2]=d2; s_redd[wid*4+3]=d3; }
        }
        __syncthreads();
        if (tid < 4){
            float sm=0.f;
            #pragma unroll
            for (int wg=0; wg<17; wg++) sm += s_redd[wg*4+tid];
            s_dinv[d*4+tid] = 1.f/(sm + 1e-16f);
        }
        __syncthreads();
    }

    int c = tid;
    int h = c / DOUT;
    const float* Hb = g_H + nbase*HH;
    float a[8];
    #pragma unroll
    for (int d=0;d<8;d++) a[d]=0.f;
    for (int t=0; t<NN; t++){
        float hr = Hb[(size_t)t*HH + c];
        float4 w0 = *(const float4*)&s_wt[t*40 + h*8];
        float4 w1 = *(const float4*)&s_wt[t*40 + h*8 + 4];
        a[0] += w0.x*hr; a[1] += w0.y*hr; a[2] += w0.z*hr; a[3] += w0.w*hr;
        a[4] += w1.x*hr; a[5] += w1.y*hr; a[6] += w1.z*hr; a[7] += w1.w*hr;
    }
    float y[8];
    float bi = bias[c];
    #pragma unroll
    for (int d=0;d<8;d++){
        float agg = a[d]*s_dinv[d*4+h];
        y[d] = fmaxf(agg + bi, 0.f) + g_X[cur][(nbase + TT + d)*HH + c];
    }

    float gm = gamma[c], bt = beta[c];
    for (int d=0;d<8;d++){
        float ps = warpSum(y[d]);
        float pq = warpSum(y[d]*y[d]);
        if (lane==0){ s_red[wid]=ps; s_red2[wid]=pq; }
        __syncthreads();
        if (tid==0){
            float S=0.f,Q=0.f;
            #pragma unroll
            for (int wg=0;wg<24;wg++){ S+=s_red[wg]; Q+=s_red2[wg]; }
            float mean = S*(1.f/HH);
            float var  = Q*(1.f/HH) - mean*mean;
            s_stats[0]=mean;
            s_stats[1]=rsqrtf(fmaxf(var,0.f)+1e-5f);
        }
        __syncthreads();
        float mean=s_stats[0], rstd=s_stats[1];
        size_t row = (nbase + TT + d)*HH;
        float o = (y[d]-mean)*rstd*gm + bt;
        g_X[cur^1][row + c] = o;
        __nv_bfloat16 hh = __float2bfloat16(o);
        g_Ahi[row + c] = hh;
        g_Alo[row + c] = bflo(o, hh);
    }
}

// ---------------- launch ----------------
extern "C" void kernel_launch(void* const* d_in, const int* in_sizes, int n_in,
                              void* d_out, int out_size)
{
    const float* text = (const float*)d_in[0];
    const float* lab  = (const float*)d_in[1];
    const float* img  = (const float*)d_in[2];
    const float* Ws   = (const float*)d_in[3];
    const float* aws  = (const float*)d_in[4];
    const float* awd  = (const float*)d_in[5];
    const float* bias = (const float*)d_in[6];
    const float* gam  = (const float*)d_in[7];
    const float* bet  = (const float*)d_in[8];
    float* outp = (float*)d_out;

    cudaFuncSetAttribute(k_gemm_mma, cudaFuncAttributeMaxDynamicSharedMemorySize, GSMEM);
    cudaFuncSetAttribute(k_heavy2, cudaFuncAttributeMaxDynamicSharedMemorySize, HV_WSZ*4);

    k_wconv<<<(3*HH*HH + 255)/256, 256>>>(Ws);
    {
        size_t total = (size_t)BATCH*NN*H4;
        int blocks = (int)((total + 255)/256);
        k_concat<<<blocks,256>>>((const float4*)text,(const float4*)lab,(const float4*)img);
    }
    k_excl<<<BATCH,256>>>(text, lab, img);

    int cur = 0;
    for (int l=0;l<3;l++){
        k_zero<<<(2*ASZ + 255)/256, 256>>>();
        k_gemm_mma<<<dim3((BATCH*NN)/128, HH/128), 128, GSMEM>>>(l, aws + l*HH, awd + l*HH);
        int last = (l==2);
        k_text<<<(BATCH*TT)/8,256>>>(cur, bias+l*HH, gam+l*HH, bet+l*HH, outp, last);
        if (!last) k_heavy2<<<BATCH, 768, HV_WSZ*4>>>(cur, bias+l*HH, gam+l*HH, bet+l*HH);
        cur ^= 1;
    }
}